// round 2
// baseline (speedup 1.0000x reference)
#include <cuda_runtime.h>

// ---------------------------------------------------------------------------
// EGNN layer, fused fp32 implementation with packed f32x2 FFMA (sm_103a FFMA2).
//   Output: concat(h_out[N,128], x_out[N,3], v_out[N,3]) as fp32.
// ---------------------------------------------------------------------------

#define TE   64      // edges (or nodes) per CTA
#define LDA  132     // smem row stride (floats)
#define S1LD 65      // stride for the [64,64] inf hidden tile
#define MAXN 50016

typedef unsigned long long u64;

__device__ float  g_mi[(size_t)MAXN * 128];   // segment-sum of e_ij * m_ij
__device__ float4 g_agg[MAXN];                // xyz: x_update sum, w: degree

// shared memory carve (floats)
#define OFF_A  0
#define OFF_B  (TE * LDA)            //  8448
#define OFF_C  (2 * TE * LDA)        // 16896
#define OFF_W  (3 * TE * LDA)        // 25344 : 2 x (8x128) weight ping-pong
#define OFF_X  (OFF_W + 2048)        // 27392 : per-edge scalars [64][8]
#define OFF_R  (OFF_X + TE * 8)      // 27904
#define OFF_CC (OFF_R + TE)          // 27968
#define SMEM_FLOATS (OFF_CC + TE)    // 28032
#define SMEM_BYTES  (SMEM_FLOATS * 4)  // 112128 bytes -> 2 CTAs / SM

__device__ __forceinline__ float siluf(float v) {
    return v * (1.0f / (1.0f + __expf(-v)));
}

__device__ __forceinline__ u64 dup2(float a) {
    u64 r; asm("mov.b64 %0, {%1, %1};" : "=l"(r) : "f"(a)); return r;
}
__device__ __forceinline__ void ffma2(u64& d, u64 a, u64 b) {
    asm("fma.rn.f32x2 %0, %1, %2, %0;" : "+l"(d) : "l"(a), "l"(b));
}
__device__ __forceinline__ float2 unpk(u64 v) {
    float2 f; asm("mov.b64 {%0, %1}, %2;" : "=f"(f.x), "=f"(f.y) : "l"(v)); return f;
}

// acc[i][0..1] cover cols tx*4..tx*4+3 ; acc[i][2..3] cover cols 64+tx*4..+3
__device__ __forceinline__ void init_acc(u64 acc[4][4], const float* __restrict__ bias, int tx) {
    ulonglong2 lo = __ldg((const ulonglong2*)(bias + tx * 4));
    ulonglong2 hi = __ldg((const ulonglong2*)(bias + 64 + tx * 4));
#pragma unroll
    for (int i = 0; i < 4; ++i) {
        acc[i][0] = lo.x; acc[i][1] = lo.y; acc[i][2] = hi.x; acc[i][3] = hi.y;
    }
}

// C[64,128] += A[64,K] @ W[K,128]; A in smem (stride LDA), W global row-major.
// 256 threads = 16 ty (4 rows) x 16 tx (8 cols, split-64 mapping).
// Ping-pong weight staging: one __syncthreads per 8-K tile; next tile's LDG
// overlaps this tile's FFMA2. First sync also serves as the caller's barrier.
__device__ __forceinline__ void gemm_acc(u64 acc[4][4], const float* __restrict__ As,
                                         const float* __restrict__ Wg, int K,
                                         float* wt, int tid, int ty, int tx) {
    ((float4*)wt)[tid] = __ldg((const float4*)Wg + tid);   // stage tile 0 -> w0
    const int nt = K >> 3;
    for (int t = 0; t < nt; ++t) {
        __syncthreads();
        const float* wc = wt + ((t & 1) ? 1024 : 0);
        if (t + 1 < nt) {
            float* wn = wt + ((t & 1) ? 0 : 1024);
            ((float4*)wn)[tid] = __ldg((const float4*)(Wg + (t + 1) * 1024) + tid);
        }
        const float* ap = As + (ty * 4) * LDA + t * 8;
#pragma unroll
        for (int kk = 0; kk < 8; kk += 4) {
            float4 a4[4];
#pragma unroll
            for (int i = 0; i < 4; ++i)
                a4[i] = *(const float4*)(ap + i * LDA + kk);
#pragma unroll
            for (int k = 0; k < 4; ++k) {
                ulonglong2 blo = *(const ulonglong2*)(wc + (kk + k) * 128 + tx * 4);
                ulonglong2 bhi = *(const ulonglong2*)(wc + (kk + k) * 128 + 64 + tx * 4);
#pragma unroll
                for (int i = 0; i < 4; ++i) {
                    float av = (k == 0) ? a4[i].x : (k == 1) ? a4[i].y
                             : (k == 2) ? a4[i].z : a4[i].w;
                    u64 a2 = dup2(av);
                    ffma2(acc[i][0], a2, blo.x);
                    ffma2(acc[i][1], a2, blo.y);
                    ffma2(acc[i][2], a2, bhi.x);
                    ffma2(acc[i][3], a2, bhi.y);
                }
            }
        }
    }
}

// C[64,64] += A[64,K] @ W[K,64]; 32 ty2 (2 rows) x 8 tx2 (8 cols split-32).
// Uses wt+0 / wt+1024 ping-pong (same parity footprint as the 128-wide gemm).
__device__ __forceinline__ void gemm_acc64(u64 acc[2][4], const float* __restrict__ As,
                                           const float* __restrict__ Wg, int K,
                                           float* wt, int tid, int ty2, int tx2) {
    if (tid < 128) ((float4*)wt)[tid] = __ldg((const float4*)Wg + tid);
    const int nt = K >> 3;
    for (int t = 0; t < nt; ++t) {
        __syncthreads();
        const float* wc = wt + ((t & 1) ? 1024 : 0);
        if (t + 1 < nt && tid < 128) {
            float* wn = wt + ((t & 1) ? 0 : 1024);
            ((float4*)wn)[tid] = __ldg((const float4*)(Wg + (t + 1) * 512) + tid);
        }
        const float* ap = As + (ty2 * 2) * LDA + t * 8;
#pragma unroll
        for (int kk = 0; kk < 8; kk += 4) {
            float4 a0 = *(const float4*)(ap + kk);
            float4 a1 = *(const float4*)(ap + LDA + kk);
#pragma unroll
            for (int k = 0; k < 4; ++k) {
                ulonglong2 blo = *(const ulonglong2*)(wc + (kk + k) * 64 + tx2 * 4);
                ulonglong2 bhi = *(const ulonglong2*)(wc + (kk + k) * 64 + 32 + tx2 * 4);
                float v0 = (k == 0) ? a0.x : (k == 1) ? a0.y : (k == 2) ? a0.z : a0.w;
                float v1 = (k == 0) ? a1.x : (k == 1) ? a1.y : (k == 2) ? a1.z : a1.w;
                u64 d0 = dup2(v0), d1 = dup2(v1);
                ffma2(acc[0][0], d0, blo.x); ffma2(acc[0][1], d0, blo.y);
                ffma2(acc[0][2], d0, bhi.x); ffma2(acc[0][3], d0, bhi.y);
                ffma2(acc[1][0], d1, blo.x); ffma2(acc[1][1], d1, blo.y);
                ffma2(acc[1][2], d1, bhi.x); ffma2(acc[1][3], d1, bhi.y);
            }
        }
    }
}

template <bool ACT>
__device__ __forceinline__ void store_tile(const u64 acc[4][4], float* C, int ty, int tx) {
#pragma unroll
    for (int i = 0; i < 4; ++i) {
        float2 p0 = unpk(acc[i][0]), p1 = unpk(acc[i][1]);
        float2 p2 = unpk(acc[i][2]), p3 = unpk(acc[i][3]);
        float4 lo, hi;
        lo.x = ACT ? siluf(p0.x) : p0.x;  lo.y = ACT ? siluf(p0.y) : p0.y;
        lo.z = ACT ? siluf(p1.x) : p1.x;  lo.w = ACT ? siluf(p1.y) : p1.y;
        hi.x = ACT ? siluf(p2.x) : p2.x;  hi.y = ACT ? siluf(p2.y) : p2.y;
        hi.z = ACT ? siluf(p3.x) : p3.x;  hi.w = ACT ? siluf(p3.y) : p3.y;
        float* p = C + (ty * 4 + i) * LDA + tx * 4;
        *(float4*)p = lo;
        *(float4*)(p + 64) = hi;
    }
}

__global__ void egnn_zero_kernel(int N) {
    int total = N * 32;
    for (int i = blockIdx.x * blockDim.x + threadIdx.x; i < total + N;
         i += gridDim.x * blockDim.x) {
        if (i < total)
            ((float4*)g_mi)[i] = make_float4(0.f, 0.f, 0.f, 0.f);
        else
            g_agg[i - total] = make_float4(0.f, 0.f, 0.f, 0.f);
    }
}

__global__ void __launch_bounds__(256, 2)
egnn_edge_kernel(const float* __restrict__ h, const float* __restrict__ x,
                 const float* __restrict__ eattr, const int* __restrict__ ei,
                 int E, int N,
                 const float* __restrict__ eW1, const float* __restrict__ eb1,
                 const float* __restrict__ eW2, const float* __restrict__ eb2,
                 const float* __restrict__ cW1, const float* __restrict__ cb1,
                 const float* __restrict__ cW2,
                 const float* __restrict__ iW1, const float* __restrict__ ib1,
                 const float* __restrict__ iW2, const float* __restrict__ ib2) {
    extern __shared__ float sm[];
    float* bufA = sm + OFF_A;   // h[row] tile -> later m_ij
    float* bufB = sm + OFF_B;   // h[col] tile -> later s1 (inf hidden)
    float* bufC = sm + OFF_C;   // m1 -> later c1 (coord hidden)
    float* wt   = sm + OFF_W;
    float* xda  = sm + OFF_X;   // [64][8]: dx,dy,dz,dist,attr,e,phi,valid
    int* ridx = (int*)(sm + OFF_R);
    int* cidx = (int*)(sm + OFF_CC);

    const int tid = threadIdx.x;
    const int tx = tid & 15, ty = tid >> 4;
    const int e0 = blockIdx.x * TE;

    if (tid < TE) {
        int e = e0 + tid;
        int r = 0, c = 0;
        float at = 0.f, valid = 0.f;
        if (e < E) { r = ei[e]; c = ei[E + e]; at = eattr[e]; valid = 1.f; }
        float dx = x[r * 3 + 0] - x[c * 3 + 0];
        float dy = x[r * 3 + 1] - x[c * 3 + 1];
        float dz = x[r * 3 + 2] - x[c * 3 + 2];
        xda[tid * 8 + 0] = dx; xda[tid * 8 + 1] = dy; xda[tid * 8 + 2] = dz;
        xda[tid * 8 + 3] = dx * dx + dy * dy + dz * dz;
        xda[tid * 8 + 4] = at;
        xda[tid * 8 + 7] = valid;
        ridx[tid] = r; cidx[tid] = c;
    }
    __syncthreads();

    // gather h[row], h[col] tiles (h is 25.6MB -> L2 hits)
    for (int q = tid; q < TE * 32; q += 256) {
        int t = q >> 5, k4 = q & 31;
        int r = ridx[t], c = cidx[t];
        ((float4*)(bufA + t * LDA))[k4] = __ldg((const float4*)h + r * 32 + k4);
        ((float4*)(bufB + t * LDA))[k4] = __ldg((const float4*)h + c * 32 + k4);
    }
    // gemm_acc's first internal __syncthreads covers the gather

    u64 acc[4][4];

    // ---- m1 = silu(ef @ edge_W1 + b1), K = 258 ----
    init_acc(acc, eb1, tx);
    gemm_acc(acc, bufA, eW1, 128, wt, tid, ty, tx);
    gemm_acc(acc, bufB, eW1 + 128 * 128, 128, wt, tid, ty, tx);
    {   // K tail: rows 256 (dist_sq), 257 (edge_attr)
        const float* w256 = eW1 + 256 * 128;
        const float* w257 = eW1 + 257 * 128;
        ulonglong2 wa0 = __ldg((const ulonglong2*)(w256 + tx * 4));
        ulonglong2 wa1 = __ldg((const ulonglong2*)(w256 + 64 + tx * 4));
        ulonglong2 wb0 = __ldg((const ulonglong2*)(w257 + tx * 4));
        ulonglong2 wb1 = __ldg((const ulonglong2*)(w257 + 64 + tx * 4));
#pragma unroll
        for (int i = 0; i < 4; ++i) {
            u64 dd = dup2(xda[(ty * 4 + i) * 8 + 3]);
            u64 aa = dup2(xda[(ty * 4 + i) * 8 + 4]);
            ffma2(acc[i][0], dd, wa0.x); ffma2(acc[i][1], dd, wa0.y);
            ffma2(acc[i][2], dd, wa1.x); ffma2(acc[i][3], dd, wa1.y);
            ffma2(acc[i][0], aa, wb0.x); ffma2(acc[i][1], aa, wb0.y);
            ffma2(acc[i][2], aa, wb1.x); ffma2(acc[i][3], aa, wb1.y);
        }
    }
    store_tile<true>(acc, bufC, ty, tx);   // m1

    // ---- m_ij = silu(m1 @ edge_W2 + b2) ----
    init_acc(acc, eb2, tx);
    gemm_acc(acc, bufC, eW2, 128, wt, tid, ty, tx);
    store_tile<true>(acc, bufA, ty, tx);   // m_ij (overwrites h[row] tile)

    // ---- s1 = silu(m_ij @ inf_W1 + inf_b1) : [64,64] ----
    {
        const int tx2 = tid & 7, ty2 = tid >> 3;
        u64 acc2[2][4];
        ulonglong2 lo = __ldg((const ulonglong2*)(ib1 + tx2 * 4));
        ulonglong2 hi = __ldg((const ulonglong2*)(ib1 + 32 + tx2 * 4));
        acc2[0][0] = lo.x; acc2[0][1] = lo.y; acc2[0][2] = hi.x; acc2[0][3] = hi.y;
#pragma unroll
        for (int j = 0; j < 4; ++j) acc2[1][j] = acc2[0][j];
        gemm_acc64(acc2, bufA, iW1, 128, wt, tid, ty2, tx2);
#pragma unroll
        for (int i = 0; i < 2; ++i) {
            float2 p0 = unpk(acc2[i][0]), p1 = unpk(acc2[i][1]);
            float2 p2 = unpk(acc2[i][2]), p3 = unpk(acc2[i][3]);
            float* pr = bufB + (ty2 * 2 + i) * S1LD + tx2 * 4;
            pr[0] = siluf(p0.x); pr[1] = siluf(p0.y);
            pr[2] = siluf(p1.x); pr[3] = siluf(p1.y);
            pr[32] = siluf(p2.x); pr[33] = siluf(p2.y);
            pr[34] = siluf(p3.x); pr[35] = siluf(p3.y);
        }
    }

    // ---- c1 = silu(m_ij @ coord_W1 + coord_b1) ----
    init_acc(acc, cb1, tx);
    gemm_acc(acc, bufA, cW1, 128, wt, tid, ty, tx);
    store_tile<true>(acc, bufC, ty, tx);   // c1

    __syncthreads();
    if (tid < 64) wt[tid] = __ldg(iW2 + tid);
    if (tid >= 64 && tid < 192) wt[tid] = __ldg(cW2 + tid - 64);
    __syncthreads();

    // ---- e_ij, phi_x scalars ----
    if (tid < TE) {
        const float* srow = bufB + tid * S1LD;
        float s = __ldg(ib2);
#pragma unroll 8
        for (int k = 0; k < 64; ++k) s += srow[k] * wt[k];
        float ev = 1.f / (1.f + __expf(-s));
        const float* crow = bufC + tid * LDA;
        float p = 0.f;
#pragma unroll 8
        for (int k = 0; k < 128; ++k) p += crow[k] * wt[64 + k];
        xda[tid * 8 + 5] = ev;
        xda[tid * 8 + 6] = p;
    }
    __syncthreads();

    // ---- scatter: x_update + degree (one float4 atomic / edge) ----
    if (tid < TE && xda[tid * 8 + 7] != 0.f) {
        float ev = xda[tid * 8 + 5], p = xda[tid * 8 + 6];
        float s = ev * p;
        atomicAdd(&g_agg[ridx[tid]],
                  make_float4(s * xda[tid * 8 + 0], s * xda[tid * 8 + 1],
                              s * xda[tid * 8 + 2], 1.0f));
    }
    // ---- scatter: m_i += e_ij * m_ij (float4 vector atomics) ----
    for (int q = tid; q < TE * 32; q += 256) {
        int t = q >> 5, k4 = q & 31;
        if (xda[t * 8 + 7] != 0.f) {
            float ev = xda[t * 8 + 5];
            float4 m = ((float4*)(bufA + t * LDA))[k4];
            m.x *= ev; m.y *= ev; m.z *= ev; m.w *= ev;
            atomicAdd(((float4*)g_mi) + ridx[t] * 32 + k4, m);
        }
    }
}

__global__ void __launch_bounds__(256, 2)
egnn_node_kernel(const float* __restrict__ h, const float* __restrict__ x,
                 const float* __restrict__ vinit, int N,
                 const float* __restrict__ nW1, const float* __restrict__ nb1,
                 const float* __restrict__ nW2, const float* __restrict__ nb2,
                 const float* __restrict__ vW1, const float* __restrict__ vb1,
                 const float* __restrict__ vW2,
                 float* __restrict__ out_h, float* __restrict__ out_x,
                 float* __restrict__ out_v) {
    extern __shared__ float sm[];
    float* bufA = sm + OFF_A;   // h tile
    float* bufB = sm + OFF_B;   // m_i tile
    float* bufC = sm + OFF_C;   // t1 -> n1
    float* wt   = sm + OFF_W;

    const int tid = threadIdx.x;
    const int tx = tid & 15, ty = tid >> 4;
    const int n0 = blockIdx.x * TE;

    for (int q = tid; q < TE * 32; q += 256) {
        int t = q >> 5, k4 = q & 31;
        int n = n0 + t;
        if (n >= N) n = N - 1;
        ((float4*)(bufA + t * LDA))[k4] = __ldg((const float4*)h + n * 32 + k4);
        ((float4*)(bufB + t * LDA))[k4] = ((const float4*)g_mi)[n * 32 + k4];
    }

    u64 acc[4][4];

    // ---- t1 = silu(h @ vel_W1 + vel_b1) ----
    init_acc(acc, vb1, tx);
    gemm_acc(acc, bufA, vW1, 128, wt, tid, ty, tx);
    store_tile<true>(acc, bufC, ty, tx);
    __syncthreads();
    if (tid < 128) wt[tid] = __ldg(vW2 + tid);
    __syncthreads();

    // ---- vel_scale, v_out, x_out ----
    if (tid < TE) {
        int n = n0 + tid;
        if (n < N) {
            const float* trow = bufC + tid * LDA;
            float s = 0.f;
#pragma unroll 8
            for (int k = 0; k < 128; ++k) s += trow[k] * wt[k];
            float vx = vinit[n * 3 + 0] * s;
            float vy = vinit[n * 3 + 1] * s;
            float vz = vinit[n * 3 + 2] * s;
            out_v[n * 3 + 0] = vx; out_v[n * 3 + 1] = vy; out_v[n * 3 + 2] = vz;
            float4 ag = g_agg[n];
            float inv = 1.0f / (float)(N - 1);
            float x0 = x[n * 3 + 0], x1 = x[n * 3 + 1], x2 = x[n * 3 + 2];
            if (ag.w > 0.f) {
                out_x[n * 3 + 0] = x0 + vx + ag.x * inv;
                out_x[n * 3 + 1] = x1 + vy + ag.y * inv;
                out_x[n * 3 + 2] = x2 + vz + ag.z * inv;
            } else {
                out_x[n * 3 + 0] = x0;
                out_x[n * 3 + 1] = x1;
                out_x[n * 3 + 2] = x2;
            }
        }
    }
    __syncthreads();   // protect wt (vW2) reads before next gemm's staging

    // ---- n1 = silu([h, m_i] @ node_W1 + node_b1) ----
    init_acc(acc, nb1, tx);
    gemm_acc(acc, bufA, nW1, 128, wt, tid, ty, tx);
    gemm_acc(acc, bufB, nW1 + 128 * 128, 128, wt, tid, ty, tx);
    store_tile<true>(acc, bufC, ty, tx);

    // ---- h_out = n1 @ node_W2 + node_b2 ----
    init_acc(acc, nb2, tx);
    gemm_acc(acc, bufC, nW2, 128, wt, tid, ty, tx);
#pragma unroll
    for (int i = 0; i < 4; ++i) {
        int n = n0 + ty * 4 + i;
        if (n < N) {
            float2 p0 = unpk(acc[i][0]), p1 = unpk(acc[i][1]);
            float2 p2 = unpk(acc[i][2]), p3 = unpk(acc[i][3]);
            float* p = out_h + (size_t)n * 128 + tx * 4;
            *(float4*)p = make_float4(p0.x, p0.y, p1.x, p1.y);
            *(float4*)(p + 64) = make_float4(p2.x, p2.y, p3.x, p3.y);
        }
    }
}

extern "C" void kernel_launch(void* const* d_in, const int* in_sizes, int n_in,
                              void* d_out, int out_size) {
    const float* h     = (const float*)d_in[0];
    const float* x     = (const float*)d_in[1];
    const float* eattr = (const float*)d_in[2];
    const float* vinit = (const float*)d_in[3];
    const int*   ei    = (const int*)d_in[4];
    const float* eW1 = (const float*)d_in[5];
    const float* eb1 = (const float*)d_in[6];
    const float* eW2 = (const float*)d_in[7];
    const float* eb2 = (const float*)d_in[8];
    const float* cW1 = (const float*)d_in[9];
    const float* cb1 = (const float*)d_in[10];
    const float* cW2 = (const float*)d_in[11];
    const float* iW1 = (const float*)d_in[12];
    const float* ib1 = (const float*)d_in[13];
    const float* iW2 = (const float*)d_in[14];
    const float* ib2 = (const float*)d_in[15];
    const float* nW1 = (const float*)d_in[16];
    const float* nb1 = (const float*)d_in[17];
    const float* nW2 = (const float*)d_in[18];
    const float* nb2 = (const float*)d_in[19];
    const float* vW1 = (const float*)d_in[20];
    const float* vb1 = (const float*)d_in[21];
    const float* vW2 = (const float*)d_in[22];

    int N = in_sizes[0] / 128;
    int E = in_sizes[2];

    float* out   = (float*)d_out;
    float* out_h = out;
    float* out_x = out + (size_t)N * 128;
    float* out_v = out_x + (size_t)N * 3;

    cudaFuncSetAttribute(egnn_edge_kernel,
                         cudaFuncAttributeMaxDynamicSharedMemorySize, SMEM_BYTES);
    cudaFuncSetAttribute(egnn_node_kernel,
                         cudaFuncAttributeMaxDynamicSharedMemorySize, SMEM_BYTES);

    egnn_zero_kernel<<<512, 256>>>(N);
    egnn_edge_kernel<<<(E + TE - 1) / TE, 256, SMEM_BYTES>>>(
        h, x, eattr, ei, E, N, eW1, eb1, eW2, eb2, cW1, cb1, cW2,
        iW1, ib1, iW2, ib2);
    egnn_node_kernel<<<(N + TE - 1) / TE, 256, SMEM_BYTES>>>(
        h, x, vinit, N, nW1, nb1, nW2, nb2, vW1, vb1, vW2,
        out_h, out_x, out_v);
}

// round 3
// speedup vs baseline: 1.6448x; 1.6448x over previous
#include <cuda_runtime.h>

// ---------------------------------------------------------------------------
// EGNN layer, fused fp32 implementation with packed f32x2 FFMA (sm_103a FFMA2).
//   Output: concat(h_out[N,128], x_out[N,3], v_out[N,3]) as fp32.
// ---------------------------------------------------------------------------

#define TE   64      // edges (or nodes) per CTA
#define LDA  132     // smem row stride (floats)
#define S1LD 65      // stride for the [64,64] inf hidden tile
#define MAXN 50016

typedef unsigned long long u64;

__device__ float  g_mi[(size_t)MAXN * 128];   // segment-sum of e_ij * m_ij
__device__ float4 g_agg[MAXN];                // xyz: x_update sum, w: degree

// shared memory carve (floats)
#define OFF_A  0
#define OFF_B  (TE * LDA)            //  8448
#define OFF_C  (2 * TE * LDA)        // 16896
#define OFF_W  (3 * TE * LDA)        // 25344 : 2 x (8x128) weight ping-pong
#define OFF_X  (OFF_W + 2048)        // 27392 : per-edge scalars [64][8]
#define OFF_R  (OFF_X + TE * 8)      // 27904
#define OFF_CC (OFF_R + TE)          // 27968
#define SMEM_FLOATS (OFF_CC + TE)    // 28032
#define SMEM_BYTES  (SMEM_FLOATS * 4)  // 112128 bytes -> 2 CTAs / SM

__device__ __forceinline__ float siluf(float v) {
    return v * (1.0f / (1.0f + __expf(-v)));
}

__device__ __forceinline__ u64 dup2(float a) {
    u64 r; asm("mov.b64 %0, {%1, %1};" : "=l"(r) : "f"(a)); return r;
}
__device__ __forceinline__ void ffma2(u64& d, u64 a, u64 b) {
    asm("fma.rn.f32x2 %0, %1, %2, %0;" : "+l"(d) : "l"(a), "l"(b));
}
__device__ __forceinline__ float2 unpk(u64 v) {
    float2 f; asm("mov.b64 {%0, %1}, %2;" : "=f"(f.x), "=f"(f.y) : "l"(v)); return f;
}

// acc[i][0..1] cover cols tx*4..tx*4+3 ; acc[i][2..3] cover cols 64+tx*4..+3
__device__ __forceinline__ void init_acc(u64 acc[4][4], const float* __restrict__ bias, int tx) {
    ulonglong2 lo = __ldg((const ulonglong2*)(bias + tx * 4));
    ulonglong2 hi = __ldg((const ulonglong2*)(bias + 64 + tx * 4));
#pragma unroll
    for (int i = 0; i < 4; ++i) {
        acc[i][0] = lo.x; acc[i][1] = lo.y; acc[i][2] = hi.x; acc[i][3] = hi.y;
    }
}

// C[64,128] += A[64,K] @ W[K,128]; A in smem (stride LDA), W global row-major.
// 256 threads = 16 ty (4 rows) x 16 tx (8 cols, split-64 mapping).
// Ping-pong weight staging: one __syncthreads per 8-K tile; next tile's LDG
// overlaps this tile's FFMA2. First sync also serves as the caller's barrier.
__device__ __forceinline__ void gemm_acc(u64 acc[4][4], const float* __restrict__ As,
                                         const float* __restrict__ Wg, int K,
                                         float* wt, int tid, int ty, int tx) {
    ((float4*)wt)[tid] = __ldg((const float4*)Wg + tid);   // stage tile 0 -> w0
    const int nt = K >> 3;
    for (int t = 0; t < nt; ++t) {
        __syncthreads();
        const float* wc = wt + ((t & 1) ? 1024 : 0);
        if (t + 1 < nt) {
            float* wn = wt + ((t & 1) ? 0 : 1024);
            ((float4*)wn)[tid] = __ldg((const float4*)(Wg + (t + 1) * 1024) + tid);
        }
        const float* ap = As + (ty * 4) * LDA + t * 8;
#pragma unroll
        for (int kk = 0; kk < 8; kk += 4) {
            float4 a4[4];
#pragma unroll
            for (int i = 0; i < 4; ++i)
                a4[i] = *(const float4*)(ap + i * LDA + kk);
#pragma unroll
            for (int k = 0; k < 4; ++k) {
                ulonglong2 blo = *(const ulonglong2*)(wc + (kk + k) * 128 + tx * 4);
                ulonglong2 bhi = *(const ulonglong2*)(wc + (kk + k) * 128 + 64 + tx * 4);
#pragma unroll
                for (int i = 0; i < 4; ++i) {
                    float av = (k == 0) ? a4[i].x : (k == 1) ? a4[i].y
                             : (k == 2) ? a4[i].z : a4[i].w;
                    u64 a2 = dup2(av);
                    ffma2(acc[i][0], a2, blo.x);
                    ffma2(acc[i][1], a2, blo.y);
                    ffma2(acc[i][2], a2, bhi.x);
                    ffma2(acc[i][3], a2, bhi.y);
                }
            }
        }
    }
}

// C[64,64] += A[64,K] @ W[K,64]; 32 ty2 (2 rows) x 8 tx2 (8 cols split-32).
// Uses wt+0 / wt+1024 ping-pong (same parity footprint as the 128-wide gemm).
__device__ __forceinline__ void gemm_acc64(u64 acc[2][4], const float* __restrict__ As,
                                           const float* __restrict__ Wg, int K,
                                           float* wt, int tid, int ty2, int tx2) {
    if (tid < 128) ((float4*)wt)[tid] = __ldg((const float4*)Wg + tid);
    const int nt = K >> 3;
    for (int t = 0; t < nt; ++t) {
        __syncthreads();
        const float* wc = wt + ((t & 1) ? 1024 : 0);
        if (t + 1 < nt && tid < 128) {
            float* wn = wt + ((t & 1) ? 0 : 1024);
            ((float4*)wn)[tid] = __ldg((const float4*)(Wg + (t + 1) * 512) + tid);
        }
        const float* ap = As + (ty2 * 2) * LDA + t * 8;
#pragma unroll
        for (int kk = 0; kk < 8; kk += 4) {
            float4 a0 = *(const float4*)(ap + kk);
            float4 a1 = *(const float4*)(ap + LDA + kk);
#pragma unroll
            for (int k = 0; k < 4; ++k) {
                ulonglong2 blo = *(const ulonglong2*)(wc + (kk + k) * 64 + tx2 * 4);
                ulonglong2 bhi = *(const ulonglong2*)(wc + (kk + k) * 64 + 32 + tx2 * 4);
                float v0 = (k == 0) ? a0.x : (k == 1) ? a0.y : (k == 2) ? a0.z : a0.w;
                float v1 = (k == 0) ? a1.x : (k == 1) ? a1.y : (k == 2) ? a1.z : a1.w;
                u64 d0 = dup2(v0), d1 = dup2(v1);
                ffma2(acc[0][0], d0, blo.x); ffma2(acc[0][1], d0, blo.y);
                ffma2(acc[0][2], d0, bhi.x); ffma2(acc[0][3], d0, bhi.y);
                ffma2(acc[1][0], d1, blo.x); ffma2(acc[1][1], d1, blo.y);
                ffma2(acc[1][2], d1, bhi.x); ffma2(acc[1][3], d1, bhi.y);
            }
        }
    }
}

template <bool ACT>
__device__ __forceinline__ void store_tile(const u64 acc[4][4], float* C, int ty, int tx) {
#pragma unroll
    for (int i = 0; i < 4; ++i) {
        float2 p0 = unpk(acc[i][0]), p1 = unpk(acc[i][1]);
        float2 p2 = unpk(acc[i][2]), p3 = unpk(acc[i][3]);
        float4 lo, hi;
        lo.x = ACT ? siluf(p0.x) : p0.x;  lo.y = ACT ? siluf(p0.y) : p0.y;
        lo.z = ACT ? siluf(p1.x) : p1.x;  lo.w = ACT ? siluf(p1.y) : p1.y;
        hi.x = ACT ? siluf(p2.x) : p2.x;  hi.y = ACT ? siluf(p2.y) : p2.y;
        hi.z = ACT ? siluf(p3.x) : p3.x;  hi.w = ACT ? siluf(p3.y) : p3.y;
        float* p = C + (ty * 4 + i) * LDA + tx * 4;
        *(float4*)p = lo;
        *(float4*)(p + 64) = hi;
    }
}

__global__ void egnn_zero_kernel(int N) {
    int total = N * 32;
    for (int i = blockIdx.x * blockDim.x + threadIdx.x; i < total + N;
         i += gridDim.x * blockDim.x) {
        if (i < total)
            ((float4*)g_mi)[i] = make_float4(0.f, 0.f, 0.f, 0.f);
        else
            g_agg[i - total] = make_float4(0.f, 0.f, 0.f, 0.f);
    }
}

__global__ void __launch_bounds__(256, 2)
egnn_edge_kernel(const float* __restrict__ h, const float* __restrict__ x,
                 const float* __restrict__ eattr, const int* __restrict__ ei,
                 int E, int N,
                 const float* __restrict__ eW1, const float* __restrict__ eb1,
                 const float* __restrict__ eW2, const float* __restrict__ eb2,
                 const float* __restrict__ cW1, const float* __restrict__ cb1,
                 const float* __restrict__ cW2,
                 const float* __restrict__ iW1, const float* __restrict__ ib1,
                 const float* __restrict__ iW2, const float* __restrict__ ib2) {
    extern __shared__ float sm[];
    float* bufA = sm + OFF_A;   // h[row] tile -> later m_ij
    float* bufB = sm + OFF_B;   // h[col] tile -> later s1 (inf hidden)
    float* bufC = sm + OFF_C;   // m1 -> later c1 (coord hidden)
    float* wt   = sm + OFF_W;
    float* xda  = sm + OFF_X;   // [64][8]: dx,dy,dz,dist,attr,e,phi,valid
    int* ridx = (int*)(sm + OFF_R);
    int* cidx = (int*)(sm + OFF_CC);

    const int tid = threadIdx.x;
    const int tx = tid & 15, ty = tid >> 4;
    const int e0 = blockIdx.x * TE;

    if (tid < TE) {
        int e = e0 + tid;
        int r = 0, c = 0;
        float at = 0.f, valid = 0.f;
        if (e < E) { r = ei[e]; c = ei[E + e]; at = eattr[e]; valid = 1.f; }
        float dx = x[r * 3 + 0] - x[c * 3 + 0];
        float dy = x[r * 3 + 1] - x[c * 3 + 1];
        float dz = x[r * 3 + 2] - x[c * 3 + 2];
        xda[tid * 8 + 0] = dx; xda[tid * 8 + 1] = dy; xda[tid * 8 + 2] = dz;
        xda[tid * 8 + 3] = dx * dx + dy * dy + dz * dz;
        xda[tid * 8 + 4] = at;
        xda[tid * 8 + 7] = valid;
        ridx[tid] = r; cidx[tid] = c;
    }
    __syncthreads();

    // gather h[row], h[col] tiles (h is 25.6MB -> L2 hits)
    for (int q = tid; q < TE * 32; q += 256) {
        int t = q >> 5, k4 = q & 31;
        int r = ridx[t], c = cidx[t];
        ((float4*)(bufA + t * LDA))[k4] = __ldg((const float4*)h + r * 32 + k4);
        ((float4*)(bufB + t * LDA))[k4] = __ldg((const float4*)h + c * 32 + k4);
    }
    // gemm_acc's first internal __syncthreads covers the gather

    u64 acc[4][4];

    // ---- m1 = silu(ef @ edge_W1 + b1), K = 258 ----
    init_acc(acc, eb1, tx);
    gemm_acc(acc, bufA, eW1, 128, wt, tid, ty, tx);
    gemm_acc(acc, bufB, eW1 + 128 * 128, 128, wt, tid, ty, tx);
    {   // K tail: rows 256 (dist_sq), 257 (edge_attr)
        const float* w256 = eW1 + 256 * 128;
        const float* w257 = eW1 + 257 * 128;
        ulonglong2 wa0 = __ldg((const ulonglong2*)(w256 + tx * 4));
        ulonglong2 wa1 = __ldg((const ulonglong2*)(w256 + 64 + tx * 4));
        ulonglong2 wb0 = __ldg((const ulonglong2*)(w257 + tx * 4));
        ulonglong2 wb1 = __ldg((const ulonglong2*)(w257 + 64 + tx * 4));
#pragma unroll
        for (int i = 0; i < 4; ++i) {
            u64 dd = dup2(xda[(ty * 4 + i) * 8 + 3]);
            u64 aa = dup2(xda[(ty * 4 + i) * 8 + 4]);
            ffma2(acc[i][0], dd, wa0.x); ffma2(acc[i][1], dd, wa0.y);
            ffma2(acc[i][2], dd, wa1.x); ffma2(acc[i][3], dd, wa1.y);
            ffma2(acc[i][0], aa, wb0.x); ffma2(acc[i][1], aa, wb0.y);
            ffma2(acc[i][2], aa, wb1.x); ffma2(acc[i][3], aa, wb1.y);
        }
    }
    store_tile<true>(acc, bufC, ty, tx);   // m1

    // ---- m_ij = silu(m1 @ edge_W2 + b2) ----
    init_acc(acc, eb2, tx);
    gemm_acc(acc, bufC, eW2, 128, wt, tid, ty, tx);
    store_tile<true>(acc, bufA, ty, tx);   // m_ij (overwrites h[row] tile)

    // ---- s1 = silu(m_ij @ inf_W1 + inf_b1) : [64,64] ----
    {
        const int tx2 = tid & 7, ty2 = tid >> 3;
        u64 acc2[2][4];
        ulonglong2 lo = __ldg((const ulonglong2*)(ib1 + tx2 * 4));
        ulonglong2 hi = __ldg((const ulonglong2*)(ib1 + 32 + tx2 * 4));
        acc2[0][0] = lo.x; acc2[0][1] = lo.y; acc2[0][2] = hi.x; acc2[0][3] = hi.y;
#pragma unroll
        for (int j = 0; j < 4; ++j) acc2[1][j] = acc2[0][j];
        gemm_acc64(acc2, bufA, iW1, 128, wt, tid, ty2, tx2);
#pragma unroll
        for (int i = 0; i < 2; ++i) {
            float2 p0 = unpk(acc2[i][0]), p1 = unpk(acc2[i][1]);
            float2 p2 = unpk(acc2[i][2]), p3 = unpk(acc2[i][3]);
            float* pr = bufB + (ty2 * 2 + i) * S1LD + tx2 * 4;
            pr[0] = siluf(p0.x); pr[1] = siluf(p0.y);
            pr[2] = siluf(p1.x); pr[3] = siluf(p1.y);
            pr[32] = siluf(p2.x); pr[33] = siluf(p2.y);
            pr[34] = siluf(p3.x); pr[35] = siluf(p3.y);
        }
    }

    // ---- c1 = silu(m_ij @ coord_W1 + coord_b1) ----
    init_acc(acc, cb1, tx);
    gemm_acc(acc, bufA, cW1, 128, wt, tid, ty, tx);
    store_tile<true>(acc, bufC, ty, tx);   // c1

    __syncthreads();
    if (tid < 64) wt[tid] = __ldg(iW2 + tid);
    if (tid >= 64 && tid < 192) wt[tid] = __ldg(cW2 + tid - 64);
    __syncthreads();

    // ---- e_ij, phi_x scalars ----
    if (tid < TE) {
        const float* srow = bufB + tid * S1LD;
        float s = __ldg(ib2);
#pragma unroll 8
        for (int k = 0; k < 64; ++k) s += srow[k] * wt[k];
        float ev = 1.f / (1.f + __expf(-s));
        const float* crow = bufC + tid * LDA;
        float p = 0.f;
#pragma unroll 8
        for (int k = 0; k < 128; ++k) p += crow[k] * wt[64 + k];
        xda[tid * 8 + 5] = ev;
        xda[tid * 8 + 6] = p;
    }
    __syncthreads();

    // ---- scatter: x_update + degree (one float4 atomic / edge) ----
    if (tid < TE && xda[tid * 8 + 7] != 0.f) {
        float ev = xda[tid * 8 + 5], p = xda[tid * 8 + 6];
        float s = ev * p;
        atomicAdd(&g_agg[ridx[tid]],
                  make_float4(s * xda[tid * 8 + 0], s * xda[tid * 8 + 1],
                              s * xda[tid * 8 + 2], 1.0f));
    }
    // ---- scatter: m_i += e_ij * m_ij (float4 vector atomics) ----
    for (int q = tid; q < TE * 32; q += 256) {
        int t = q >> 5, k4 = q & 31;
        if (xda[t * 8 + 7] != 0.f) {
            float ev = xda[t * 8 + 5];
            float4 m = ((float4*)(bufA + t * LDA))[k4];
            m.x *= ev; m.y *= ev; m.z *= ev; m.w *= ev;
            atomicAdd(((float4*)g_mi) + ridx[t] * 32 + k4, m);
        }
    }
}

__global__ void __launch_bounds__(256, 2)
egnn_node_kernel(const float* __restrict__ h, const float* __restrict__ x,
                 const float* __restrict__ vinit, int N,
                 const float* __restrict__ nW1, const float* __restrict__ nb1,
                 const float* __restrict__ nW2, const float* __restrict__ nb2,
                 const float* __restrict__ vW1, const float* __restrict__ vb1,
                 const float* __restrict__ vW2,
                 float* __restrict__ out_h, float* __restrict__ out_x,
                 float* __restrict__ out_v) {
    extern __shared__ float sm[];
    float* bufA = sm + OFF_A;   // h tile
    float* bufB = sm + OFF_B;   // m_i tile
    float* bufC = sm + OFF_C;   // t1 -> n1
    float* wt   = sm + OFF_W;

    const int tid = threadIdx.x;
    const int tx = tid & 15, ty = tid >> 4;
    const int n0 = blockIdx.x * TE;

    for (int q = tid; q < TE * 32; q += 256) {
        int t = q >> 5, k4 = q & 31;
        int n = n0 + t;
        if (n >= N) n = N - 1;
        ((float4*)(bufA + t * LDA))[k4] = __ldg((const float4*)h + n * 32 + k4);
        ((float4*)(bufB + t * LDA))[k4] = ((const float4*)g_mi)[n * 32 + k4];
    }

    u64 acc[4][4];

    // ---- t1 = silu(h @ vel_W1 + vel_b1) ----
    init_acc(acc, vb1, tx);
    gemm_acc(acc, bufA, vW1, 128, wt, tid, ty, tx);
    store_tile<true>(acc, bufC, ty, tx);
    __syncthreads();
    if (tid < 128) wt[tid] = __ldg(vW2 + tid);
    __syncthreads();

    // ---- vel_scale, v_out, x_out ----
    if (tid < TE) {
        int n = n0 + tid;
        if (n < N) {
            const float* trow = bufC + tid * LDA;
            float s = 0.f;
#pragma unroll 8
            for (int k = 0; k < 128; ++k) s += trow[k] * wt[k];
            float vx = vinit[n * 3 + 0] * s;
            float vy = vinit[n * 3 + 1] * s;
            float vz = vinit[n * 3 + 2] * s;
            out_v[n * 3 + 0] = vx; out_v[n * 3 + 1] = vy; out_v[n * 3 + 2] = vz;
            float4 ag = g_agg[n];
            float inv = 1.0f / (float)(N - 1);
            float x0 = x[n * 3 + 0], x1 = x[n * 3 + 1], x2 = x[n * 3 + 2];
            if (ag.w > 0.f) {
                out_x[n * 3 + 0] = x0 + vx + ag.x * inv;
                out_x[n * 3 + 1] = x1 + vy + ag.y * inv;
                out_x[n * 3 + 2] = x2 + vz + ag.z * inv;
            } else {
                out_x[n * 3 + 0] = x0;
                out_x[n * 3 + 1] = x1;
                out_x[n * 3 + 2] = x2;
            }
        }
    }
    __syncthreads();   // protect wt (vW2) reads before next gemm's staging

    // ---- n1 = silu([h, m_i] @ node_W1 + node_b1) ----
    init_acc(acc, nb1, tx);
    gemm_acc(acc, bufA, nW1, 128, wt, tid, ty, tx);
    gemm_acc(acc, bufB, nW1 + 128 * 128, 128, wt, tid, ty, tx);
    store_tile<true>(acc, bufC, ty, tx);

    // ---- h_out = n1 @ node_W2 + node_b2 ----
    init_acc(acc, nb2, tx);
    gemm_acc(acc, bufC, nW2, 128, wt, tid, ty, tx);
#pragma unroll
    for (int i = 0; i < 4; ++i) {
        int n = n0 + ty * 4 + i;
        if (n < N) {
            float2 p0 = unpk(acc[i][0]), p1 = unpk(acc[i][1]);
            float2 p2 = unpk(acc[i][2]), p3 = unpk(acc[i][3]);
            float* p = out_h + (size_t)n * 128 + tx * 4;
            *(float4*)p = make_float4(p0.x, p0.y, p1.x, p1.y);
            *(float4*)(p + 64) = make_float4(p2.x, p2.y, p3.x, p3.y);
        }
    }
}

extern "C" void kernel_launch(void* const* d_in, const int* in_sizes, int n_in,
                              void* d_out, int out_size) {
    const float* h     = (const float*)d_in[0];
    const float* x     = (const float*)d_in[1];
    const float* eattr = (const float*)d_in[2];
    const float* vinit = (const float*)d_in[3];
    const int*   ei    = (const int*)d_in[4];
    const float* eW1 = (const float*)d_in[5];
    const float* eb1 = (const float*)d_in[6];
    const float* eW2 = (const float*)d_in[7];
    const float* eb2 = (const float*)d_in[8];
    const float* cW1 = (const float*)d_in[9];
    const float* cb1 = (const float*)d_in[10];
    const float* cW2 = (const float*)d_in[11];
    const float* iW1 = (const float*)d_in[12];
    const float* ib1 = (const float*)d_in[13];
    const float* iW2 = (const float*)d_in[14];
    const float* ib2 = (const float*)d_in[15];
    const float* nW1 = (const float*)d_in[16];
    const float* nb1 = (const float*)d_in[17];
    const float* nW2 = (const float*)d_in[18];
    const float* nb2 = (const float*)d_in[19];
    const float* vW1 = (const float*)d_in[20];
    const float* vb1 = (const float*)d_in[21];
    const float* vW2 = (const float*)d_in[22];

    int N = in_sizes[0] / 128;
    int E = in_sizes[2];

    float* out   = (float*)d_out;
    float* out_h = out;
    float* out_x = out + (size_t)N * 128;
    float* out_v = out_x + (size_t)N * 3;

    cudaFuncSetAttribute(egnn_edge_kernel,
                         cudaFuncAttributeMaxDynamicSharedMemorySize, SMEM_BYTES);
    cudaFuncSetAttribute(egnn_node_kernel,
                         cudaFuncAttributeMaxDynamicSharedMemorySize, SMEM_BYTES);

    egnn_zero_kernel<<<512, 256>>>(N);
    egnn_edge_kernel<<<(E + TE - 1) / TE, 256, SMEM_BYTES>>>(
        h, x, eattr, ei, E, N, eW1, eb1, eW2, eb2, cW1, cb1, cW2,
        iW1, ib1, iW2, ib2);
    egnn_node_kernel<<<(N + TE - 1) / TE, 256, SMEM_BYTES>>>(
        h, x, vinit, N, nW1, nb1, nW2, nb2, vW1, vb1, vW2,
        out_h, out_x, out_v);
}

// round 5
// speedup vs baseline: 2.5606x; 1.5568x over previous
#include <cuda_runtime.h>
#include <cuda_bf16.h>
#include <cstdint>

// ===========================================================================
// EGNN layer. Edge MLPs on mma.sync bf16 (3-pass hi/lo split ~ fp32 accuracy).
// Node MLPs scalar fp32. Output: concat(h_out[N,128], x_out[N,3], v_out[N,3]).
// NOTE: harness ptxas targets plain sm_103 -> no tcgen05; use HMMA mma.sync.
// ===========================================================================

#define MAXN 50016
__device__ float  g_mi[(size_t)MAXN * 128];
__device__ float4 g_agg[MAXN];
// weight images: W^T [N][K] row-major bf16, row stride 136 elems (272B), hi then lo.
// chunks: eW1a@0, eW1b@69632, eW2@139264, cW1@208896 (each hi 34816 + lo 34816),
//         iW1@278528 (hi 17408 + lo 17408). total 313344.
__device__ __align__(16) unsigned char g_wimg[313344];

#define IMG_E1A 0
#define IMG_E1B 69632
#define IMG_E2  139264
#define IMG_C1  208896
#define IMG_I1  278528
#define BROW    272          // bytes per image row (136 bf16)
#define HALF_B  34816        // hi->lo offset (128-row tiles)
#define HALF_I  17408        // hi->lo offset (64-row tile)

// ---- smem layout (bytes) ----
#define SA_HI   0
#define SA_LO   34816
#define SB0     69632        // hi+lo contiguous (69632)
#define SB1     139264
#define SCST    208896       // 928 floats
#define SXDA    212608       // 128*8 floats
#define SRIDX   216704
#define SCIDX   217216
#define E_SMEM  217728

__device__ __forceinline__ uint32_t smem_u32(const void* p) {
    uint32_t a;
    asm("{ .reg .u64 t; cvta.to.shared.u64 t, %1; cvt.u32.u64 %0, t; }" : "=r"(a) : "l"(p));
    return a;
}
__device__ __forceinline__ void ldm4(uint32_t r[4], uint32_t addr) {
    asm volatile("ldmatrix.sync.aligned.m8n8.x4.shared.b16 {%0,%1,%2,%3}, [%4];"
        : "=r"(r[0]), "=r"(r[1]), "=r"(r[2]), "=r"(r[3]) : "r"(addr));
}
__device__ __forceinline__ void mma16816(float4& d, const uint32_t a[4], uint32_t b0, uint32_t b1) {
    asm volatile("mma.sync.aligned.m16n8k16.row.col.f32.bf16.bf16.f32 "
        "{%0,%1,%2,%3}, {%4,%5,%6,%7}, {%8,%9}, {%0,%1,%2,%3};"
        : "+f"(d.x), "+f"(d.y), "+f"(d.z), "+f"(d.w)
        : "r"(a[0]), "r"(a[1]), "r"(a[2]), "r"(a[3]), "r"(b0), "r"(b1));
}
#define CP16(dst, src) \
    asm volatile("cp.async.cg.shared.global [%0], [%1], 16;" :: "r"(dst), "l"(src))
#define CP_COMMIT() asm volatile("cp.async.commit_group;" ::: "memory")
#define CP_WAIT(n)  asm volatile("cp.async.wait_group %0;" :: "n"(n) : "memory")

// ---- MUFU-free silu ----
__device__ __forceinline__ float fexp_neg(float v) {   // exp(-v)
    float t = fminf(fmaxf(v, -30.f), 30.f) * -1.44269504f;
    float r = t + 12582912.f;
    int   k = __float_as_int(r) - 0x4B400000;
    float f = t - (r - 12582912.f);
    float g = f * 0.69314718f;
    float p = 1.f + g * (1.f + g * (0.5f + g * (0.16666667f + g * (0.041666667f
            + g * (8.3333333e-3f + g * 1.3888889e-3f)))));
    return p * __int_as_float((k + 127) << 23);
}
__device__ __forceinline__ float frcp(float d) {
    float y = __int_as_float(0x7EF311C3 - __float_as_int(d));
    y = y * (2.f - d * y); y = y * (2.f - d * y); y = y * (2.f - d * y);
    return y;
}
__device__ __forceinline__ float fsig(float v)  { return frcp(1.f + fexp_neg(v)); }
__device__ __forceinline__ float siluf(float v) { return v * fsig(v); }

// ---- weight prep: W[K,N] -> W^T[N,K] bf16 hi/lo padded images ----
__device__ __forceinline__ void wwrite(int base, int half, int n, int k, float w) {
    __nv_bfloat16 hi = __float2bfloat16(w);
    __nv_bfloat16 lo = __float2bfloat16(w - __bfloat162float(hi));
    int off = base + n * BROW + k * 2;
    *(__nv_bfloat16*)(g_wimg + off)        = hi;
    *(__nv_bfloat16*)(g_wimg + off + half) = lo;
}
__global__ void prep_weights(const float* __restrict__ eW1, const float* __restrict__ eW2,
                             const float* __restrict__ cW1, const float* __restrict__ iW1) {
    int i = blockIdx.x * blockDim.x + threadIdx.x;
    if (i < 16384) {
        int k = i >> 7, n = i & 127;
        wwrite(IMG_E1A, HALF_B, n, k, eW1[k * 128 + n]);
    } else if (i < 32768) {
        int j = i - 16384, k = j >> 7, n = j & 127;
        wwrite(IMG_E1B, HALF_B, n, k, eW1[(128 + k) * 128 + n]);
    } else if (i < 49152) {
        int j = i - 32768, k = j >> 7, n = j & 127;
        wwrite(IMG_E2, HALF_B, n, k, eW2[k * 128 + n]);
    } else if (i < 65536) {
        int j = i - 49152, k = j >> 7, n = j & 127;
        wwrite(IMG_C1, HALF_B, n, k, cW1[k * 128 + n]);
    } else if (i < 73728) {
        int j = i - 65536, k = j >> 6, n = j & 63;
        wwrite(IMG_I1, HALF_I, n, k, iW1[k * 64 + n]);
    }
}

__global__ void egnn_zero_kernel(int N) {
    int total = N * 32;
    for (int i = blockIdx.x * blockDim.x + threadIdx.x; i < total + N; i += gridDim.x * blockDim.x) {
        if (i < total) ((float4*)g_mi)[i] = make_float4(0.f, 0.f, 0.f, 0.f);
        else           g_agg[i - total]   = make_float4(0.f, 0.f, 0.f, 0.f);
    }
}

// ---- 3-pass split GEMM: acc[NT] += A[16,128] @ B[128, NT*8] (warp-level) ----
template <int NT>
__device__ __forceinline__ void gemm3p(float4* acc, uint32_t aHi, uint32_t aLo,
                                       uint32_t bHi, uint32_t bLo, int lane) {
    const uint32_t aoff = ((lane & 7) + ((lane >> 3) & 1) * 8) * BROW + ((lane >> 4) & 1) * 16;
    const uint32_t boff = ((lane & 7) + ((lane >> 4) & 1) * 8) * BROW + ((lane >> 3) & 1) * 16;
#pragma unroll
    for (int ks = 0; ks < 8; ++ks) {
        uint32_t ah[4], al[4];
        ldm4(ah, aHi + aoff + ks * 32);
        ldm4(al, aLo + aoff + ks * 32);
#pragma unroll
        for (int p = 0; p < NT / 2; ++p) {
            uint32_t bh[4], bl[4];
            ldm4(bh, bHi + p * 16 * BROW + boff + ks * 32);
            ldm4(bl, bLo + p * 16 * BROW + boff + ks * 32);
            mma16816(acc[2 * p],     ah, bh[0], bh[1]);
            mma16816(acc[2 * p + 1], ah, bh[2], bh[3]);
            mma16816(acc[2 * p],     al, bh[0], bh[1]);
            mma16816(acc[2 * p + 1], al, bh[2], bh[3]);
            mma16816(acc[2 * p],     ah, bl[0], bl[1]);
            mma16816(acc[2 * p + 1], ah, bl[2], bl[3]);
        }
    }
}

// split fp32 -> bf16 hi/lo pair, store 4B each to A buffers
__device__ __forceinline__ void splitst(char* smc, int row, int col, float v0, float v1) {
    __nv_bfloat16 h0 = __float2bfloat16(v0), h1 = __float2bfloat16(v1);
    __nv_bfloat162 hp; hp.x = h0; hp.y = h1;
    __nv_bfloat162 lp;
    lp.x = __float2bfloat16(v0 - __bfloat162float(h0));
    lp.y = __float2bfloat16(v1 - __bfloat162float(h1));
    int off = row * BROW + col * 2;
    *(__nv_bfloat162*)(smc + SA_HI + off) = hp;
    *(__nv_bfloat162*)(smc + SA_LO + off) = lp;
}

__device__ __forceinline__ void gatherA(char* smc, const float* __restrict__ h,
                                        const int* idx, int wid, int lane) {
    int row = wid * 16 + (lane >> 1);
    int c0 = (lane & 1) * 64;
    const float4* src = (const float4*)(h + (size_t)idx[row] * 128 + c0);
#pragma unroll
    for (int q = 0; q < 16; ++q) {
        float4 f = __ldg(src + q);
        splitst(smc, row, c0 + q * 4, f.x, f.y);
        splitst(smc, row, c0 + q * 4 + 2, f.z, f.w);
    }
}
__device__ __forceinline__ void cpyB(uint32_t dst, const unsigned char* src, int bytes, int tid) {
    for (int i = tid * 16; i < bytes; i += 256 * 16) CP16(dst + i, src + i);
    CP_COMMIT();
}

__global__ void __launch_bounds__(256, 1)
egnn_edge_mma(const float* __restrict__ h, const float* __restrict__ x,
              const float* __restrict__ eattr, const int* __restrict__ ei, int E,
              const float* __restrict__ eW1, const float* __restrict__ eb1,
              const float* __restrict__ eb2,
              const float* __restrict__ cb1, const float* __restrict__ cW2,
              const float* __restrict__ ib1, const float* __restrict__ iW2,
              const float* __restrict__ ib2) {
    extern __shared__ __align__(16) char smc[];
    uint32_t sb = smem_u32(smc);
    const int tid = threadIdx.x, wid = tid >> 5, lane = tid & 31;
    float* cst = (float*)(smc + SCST);
    float* xda = (float*)(smc + SXDA);
    int* ridx = (int*)(smc + SRIDX);
    int* cidx = (int*)(smc + SCIDX);
    const int e0 = blockIdx.x * 128;

    cpyB(sb + SB0, g_wimg + IMG_E1A, 69632, tid);   // group 1
    cpyB(sb + SB1, g_wimg + IMG_E1B, 69632, tid);   // group 2

    // consts + per-edge scalars
    if (tid < 128) {
        cst[tid]       = __ldg(eb1 + tid);
        cst[128 + tid] = __ldg(eb2 + tid);
        cst[256 + tid] = __ldg(cb1 + tid);
        cst[384 + tid] = __ldg(cW2 + tid);
        cst[512 + tid] = __ldg(eW1 + 256 * 128 + tid);
        cst[640 + tid] = __ldg(eW1 + 257 * 128 + tid);
        if (tid < 64) { cst[768 + tid] = __ldg(ib1 + tid); cst[832 + tid] = __ldg(iW2 + tid); }
        if (tid == 0) cst[896] = __ldg(ib2);
        int e = e0 + tid, r = 0, c = 0;
        float at = 0.f, valid = 0.f;
        if (e < E) { r = __ldg(ei + e); c = __ldg(ei + E + e); at = __ldg(eattr + e); valid = 1.f; }
        float dx = x[r * 3 + 0] - x[c * 3 + 0];
        float dy = x[r * 3 + 1] - x[c * 3 + 1];
        float dz = x[r * 3 + 2] - x[c * 3 + 2];
        xda[tid * 8 + 0] = dx; xda[tid * 8 + 1] = dy; xda[tid * 8 + 2] = dz;
        xda[tid * 8 + 3] = dx * dx + dy * dy + dz * dz;
        xda[tid * 8 + 4] = at; xda[tid * 8 + 7] = valid;
        ridx[tid] = r; cidx[tid] = c;
    }
    __syncthreads();                       // ridx/cidx visible for gather
    gatherA(smc, h, ridx, wid, lane);      // A = h[row] (own 16 rows)
    CP_WAIT(1); __syncthreads();           // B0 = eW1a ready

    const uint32_t aHi = sb + SA_HI + wid * 16 * BROW;
    const uint32_t aLo = sb + SA_LO + wid * 16 * BROW;
    float4 acc[16];
#pragma unroll
    for (int t = 0; t < 16; ++t) acc[t] = make_float4(0.f, 0.f, 0.f, 0.f);

    // stage 1a: h[row] @ eW1[k 0..127]
    gemm3p<16>(acc, aHi, aLo, sb + SB0, sb + SB0 + HALF_B, lane);
    __syncthreads();                       // release B0
    cpyB(sb + SB0, g_wimg + IMG_E2, 69632, tid);
    gatherA(smc, h, cidx, wid, lane);      // A = h[col]
    CP_WAIT(1); __syncthreads();           // B1 = eW1b ready

    // stage 1b: + h[col] @ eW1[k 128..255], then tail + bias + silu -> m1 -> A
    gemm3p<16>(acc, aHi, aLo, sb + SB1, sb + SB1 + HALF_B, lane);
    {
        int r0 = wid * 16 + lane / 4, r1 = r0 + 8;
        float d0 = xda[r0 * 8 + 3], a0 = xda[r0 * 8 + 4];
        float d1 = xda[r1 * 8 + 3], a1 = xda[r1 * 8 + 4];
#pragma unroll
        for (int t = 0; t < 16; ++t) {
            int c = t * 8 + (lane & 3) * 2;
            float b0 = cst[c], b1 = cst[c + 1];
            float wA0 = cst[512 + c], wA1 = cst[512 + c + 1];
            float wB0 = cst[640 + c], wB1 = cst[640 + c + 1];
            float vx = acc[t].x + b0 + d0 * wA0 + a0 * wB0;
            float vy = acc[t].y + b1 + d0 * wA1 + a0 * wB1;
            float vz = acc[t].z + b0 + d1 * wA0 + a1 * wB0;
            float vw = acc[t].w + b1 + d1 * wA1 + a1 * wB1;
            splitst(smc, r0, c, siluf(vx), siluf(vy));
            splitst(smc, r1, c, siluf(vz), siluf(vw));
            acc[t] = make_float4(0.f, 0.f, 0.f, 0.f);
        }
    }
    __syncthreads();                       // release B1 (and m1 in A is warp-private anyway)
    cpyB(sb + SB1, g_wimg + IMG_C1, 69632, tid);
    CP_WAIT(1); __syncthreads();           // B0 = eW2 ready

    // stage 2: m_ij = silu(m1 @ eW2 + b2) -> A
    gemm3p<16>(acc, aHi, aLo, sb + SB0, sb + SB0 + HALF_B, lane);
    {
        int r0 = wid * 16 + lane / 4, r1 = r0 + 8;
#pragma unroll
        for (int t = 0; t < 16; ++t) {
            int c = t * 8 + (lane & 3) * 2;
            float b0 = cst[128 + c], b1 = cst[128 + c + 1];
            splitst(smc, r0, c, siluf(acc[t].x + b0), siluf(acc[t].y + b1));
            splitst(smc, r1, c, siluf(acc[t].z + b0), siluf(acc[t].w + b1));
            acc[t] = make_float4(0.f, 0.f, 0.f, 0.f);
        }
    }
    __syncthreads();                       // release B0; m_ij visible CTA-wide
    cpyB(sb + SB0, g_wimg + IMG_I1, 34816, tid);
    CP_WAIT(1); __syncthreads();           // B1 = cW1 ready

    // stage 3: c1 = silu(m_ij @ cW1 + cb1); phi = c1 . cW2
    gemm3p<16>(acc, aHi, aLo, sb + SB1, sb + SB1 + HALF_B, lane);
    {
        int r0 = wid * 16 + lane / 4, r1 = r0 + 8;
        float p0 = 0.f, p1 = 0.f;
#pragma unroll
        for (int t = 0; t < 16; ++t) {
            int c = t * 8 + (lane & 3) * 2;
            float b0 = cst[256 + c], b1 = cst[256 + c + 1];
            float w0 = cst[384 + c], w1 = cst[384 + c + 1];
            p0 += siluf(acc[t].x + b0) * w0 + siluf(acc[t].y + b1) * w1;
            p1 += siluf(acc[t].z + b0) * w0 + siluf(acc[t].w + b1) * w1;
            acc[t] = make_float4(0.f, 0.f, 0.f, 0.f);
        }
        p0 += __shfl_xor_sync(0xFFFFFFFF, p0, 1); p1 += __shfl_xor_sync(0xFFFFFFFF, p1, 1);
        p0 += __shfl_xor_sync(0xFFFFFFFF, p0, 2); p1 += __shfl_xor_sync(0xFFFFFFFF, p1, 2);
        if ((lane & 3) == 0) { xda[r0 * 8 + 6] = p0; xda[r1 * 8 + 6] = p1; }
    }
    CP_WAIT(0); __syncthreads();           // B0 = iW1 ready; phi visible

    // stage 4: s1 = silu(m_ij @ iW1 + ib1); e = sigmoid(s1 . iW2 + ib2)
    gemm3p<8>(acc, aHi, aLo, sb + SB0, sb + SB0 + HALF_I, lane);
    {
        int r0 = wid * 16 + lane / 4, r1 = r0 + 8;
        float s0 = 0.f, s1 = 0.f;
#pragma unroll
        for (int t = 0; t < 8; ++t) {
            int c = t * 8 + (lane & 3) * 2;
            float b0 = cst[768 + c], b1 = cst[768 + c + 1];
            float w0 = cst[832 + c], w1 = cst[832 + c + 1];
            s0 += siluf(acc[t].x + b0) * w0 + siluf(acc[t].y + b1) * w1;
            s1 += siluf(acc[t].z + b0) * w0 + siluf(acc[t].w + b1) * w1;
        }
        s0 += __shfl_xor_sync(0xFFFFFFFF, s0, 1); s1 += __shfl_xor_sync(0xFFFFFFFF, s1, 1);
        s0 += __shfl_xor_sync(0xFFFFFFFF, s0, 2); s1 += __shfl_xor_sync(0xFFFFFFFF, s1, 2);
        float bi = cst[896];
        if ((lane & 3) == 0) { xda[r0 * 8 + 5] = fsig(s0 + bi); xda[r1 * 8 + 5] = fsig(s1 + bi); }
    }
    __syncthreads();                       // e visible

    // ---- scatter ----
    if (tid < 128 && xda[tid * 8 + 7] != 0.f) {
        float s = xda[tid * 8 + 5] * xda[tid * 8 + 6];
        atomicAdd(&g_agg[ridx[tid]],
                  make_float4(s * xda[tid * 8 + 0], s * xda[tid * 8 + 1],
                              s * xda[tid * 8 + 2], 1.0f));
    }
    for (int q = tid; q < 128 * 32; q += 256) {
        int t = q >> 5, k4 = q & 31;
        if (xda[t * 8 + 7] == 0.f) continue;
        float e = xda[t * 8 + 5];
        int off = t * BROW + k4 * 8;
        __nv_bfloat162 h0 = *(__nv_bfloat162*)(smc + SA_HI + off);
        __nv_bfloat162 h1 = *(__nv_bfloat162*)(smc + SA_HI + off + 4);
        __nv_bfloat162 l0 = *(__nv_bfloat162*)(smc + SA_LO + off);
        __nv_bfloat162 l1 = *(__nv_bfloat162*)(smc + SA_LO + off + 4);
        float4 m;
        m.x = (__bfloat162float(h0.x) + __bfloat162float(l0.x)) * e;
        m.y = (__bfloat162float(h0.y) + __bfloat162float(l0.y)) * e;
        m.z = (__bfloat162float(h1.x) + __bfloat162float(l1.x)) * e;
        m.w = (__bfloat162float(h1.y) + __bfloat162float(l1.y)) * e;
        atomicAdd(((float4*)g_mi) + (size_t)ridx[t] * 32 + k4, m);
    }
}

// ---------------- node kernel (validated R1 scalar fp32) ----------------
#define TEN 64
#define LDN 132
#define NO_A 0
#define NO_B (TEN * LDN)
#define NO_C (2 * TEN * LDN)
#define NO_W (3 * TEN * LDN)
#define ND_SMEM ((NO_W + 1024 + 64) * 4)

__device__ __forceinline__ void nd_init(float acc[4][8], const float* __restrict__ bias, int tx) {
    float4 b0 = __ldg((const float4*)bias + tx * 2);
    float4 b1 = __ldg((const float4*)bias + tx * 2 + 1);
#pragma unroll
    for (int i = 0; i < 4; ++i) {
        acc[i][0] = b0.x; acc[i][1] = b0.y; acc[i][2] = b0.z; acc[i][3] = b0.w;
        acc[i][4] = b1.x; acc[i][5] = b1.y; acc[i][6] = b1.z; acc[i][7] = b1.w;
    }
}
__device__ __forceinline__ void nd_gemm(float acc[4][8], const float* __restrict__ As,
                                        const float* __restrict__ Wg, int K,
                                        float* wt, int tid, int ty, int tx) {
    for (int k0 = 0; k0 < K; k0 += 8) {
        __syncthreads();
        ((float4*)wt)[tid] = __ldg((const float4*)(Wg + k0 * 128) + tid);
        __syncthreads();
        const float* ap = As + (ty * 4) * LDN + k0;
#pragma unroll
        for (int k = 0; k < 8; ++k) {
            float a[4] = {ap[k], ap[LDN + k], ap[2 * LDN + k], ap[3 * LDN + k]};
            float4 b0 = *(const float4*)(wt + k * 128 + tx * 8);
            float4 b1 = *(const float4*)(wt + k * 128 + tx * 8 + 4);
            float b[8] = {b0.x, b0.y, b0.z, b0.w, b1.x, b1.y, b1.z, b1.w};
#pragma unroll
            for (int i = 0; i < 4; ++i)
#pragma unroll
                for (int j = 0; j < 8; ++j) acc[i][j] += a[i] * b[j];
        }
    }
}
template <bool ACT>
__device__ __forceinline__ void nd_store(const float acc[4][8], float* C, int ty, int tx) {
#pragma unroll
    for (int i = 0; i < 4; ++i) {
        float4 v0, v1;
        v0.x = ACT ? siluf(acc[i][0]) : acc[i][0]; v0.y = ACT ? siluf(acc[i][1]) : acc[i][1];
        v0.z = ACT ? siluf(acc[i][2]) : acc[i][2]; v0.w = ACT ? siluf(acc[i][3]) : acc[i][3];
        v1.x = ACT ? siluf(acc[i][4]) : acc[i][4]; v1.y = ACT ? siluf(acc[i][5]) : acc[i][5];
        v1.z = ACT ? siluf(acc[i][6]) : acc[i][6]; v1.w = ACT ? siluf(acc[i][7]) : acc[i][7];
        float* p = C + (ty * 4 + i) * LDN + tx * 8;
        *(float4*)p = v0; *(float4*)(p + 4) = v1;
    }
}
__global__ void __launch_bounds__(256, 2)
egnn_node_kernel(const float* __restrict__ h, const float* __restrict__ x,
                 const float* __restrict__ vinit, int N,
                 const float* __restrict__ nW1, const float* __restrict__ nb1,
                 const float* __restrict__ nW2, const float* __restrict__ nb2,
                 const float* __restrict__ vW1, const float* __restrict__ vb1,
                 const float* __restrict__ vW2,
                 float* __restrict__ out_h, float* __restrict__ out_x, float* __restrict__ out_v) {
    extern __shared__ float smf[];
    float* bufA = smf + NO_A; float* bufB = smf + NO_B;
    float* bufC = smf + NO_C; float* wt = smf + NO_W;
    const int tid = threadIdx.x, tx = tid & 15, ty = tid >> 4;
    const int n0 = blockIdx.x * TEN;
    for (int q = tid; q < TEN * 32; q += 256) {
        int t = q >> 5, k4 = q & 31, n = n0 + t;
        if (n >= N) n = N - 1;
        ((float4*)(bufA + t * LDN))[k4] = __ldg((const float4*)h + n * 32 + k4);
        ((float4*)(bufB + t * LDN))[k4] = ((const float4*)g_mi)[n * 32 + k4];
    }
    float acc[4][8];
    nd_init(acc, vb1, tx);
    nd_gemm(acc, bufA, vW1, 128, wt, tid, ty, tx);
    nd_store<true>(acc, bufC, ty, tx);
    __syncthreads();
    if (tid < 128) wt[tid] = __ldg(vW2 + tid);
    __syncthreads();
    if (tid < TEN) {
        int n = n0 + tid;
        if (n < N) {
            const float* trow = bufC + tid * LDN;
            float s = 0.f;
#pragma unroll 8
            for (int k = 0; k < 128; ++k) s += trow[k] * wt[k];
            float vx = vinit[n * 3 + 0] * s, vy = vinit[n * 3 + 1] * s, vz = vinit[n * 3 + 2] * s;
            out_v[n * 3 + 0] = vx; out_v[n * 3 + 1] = vy; out_v[n * 3 + 2] = vz;
            float4 ag = g_agg[n];
            float inv = 1.0f / (float)(N - 1);
            float x0 = x[n * 3 + 0], x1 = x[n * 3 + 1], x2 = x[n * 3 + 2];
            if (ag.w > 0.f) {
                out_x[n * 3 + 0] = x0 + vx + ag.x * inv;
                out_x[n * 3 + 1] = x1 + vy + ag.y * inv;
                out_x[n * 3 + 2] = x2 + vz + ag.z * inv;
            } else {
                out_x[n * 3 + 0] = x0; out_x[n * 3 + 1] = x1; out_x[n * 3 + 2] = x2;
            }
        }
    }
    __syncthreads();
    nd_init(acc, nb1, tx);
    nd_gemm(acc, bufA, nW1, 128, wt, tid, ty, tx);
    nd_gemm(acc, bufB, nW1 + 128 * 128, 128, wt, tid, ty, tx);
    nd_store<true>(acc, bufC, ty, tx);
    nd_init(acc, nb2, tx);
    nd_gemm(acc, bufC, nW2, 128, wt, tid, ty, tx);
#pragma unroll
    for (int i = 0; i < 4; ++i) {
        int n = n0 + ty * 4 + i;
        if (n < N) {
            float4* p = (float4*)(out_h + (size_t)n * 128);
            p[tx * 2]     = make_float4(acc[i][0], acc[i][1], acc[i][2], acc[i][3]);
            p[tx * 2 + 1] = make_float4(acc[i][4], acc[i][5], acc[i][6], acc[i][7]);
        }
    }
}

extern "C" void kernel_launch(void* const* d_in, const int* in_sizes, int n_in,
                              void* d_out, int out_size) {
    const float* h     = (const float*)d_in[0];
    const float* x     = (const float*)d_in[1];
    const float* eattr = (const float*)d_in[2];
    const float* vinit = (const float*)d_in[3];
    const int*   ei    = (const int*)d_in[4];
    const float* eW1 = (const float*)d_in[5];
    const float* eb1 = (const float*)d_in[6];
    const float* eW2 = (const float*)d_in[7];
    const float* eb2 = (const float*)d_in[8];
    const float* cW1 = (const float*)d_in[9];
    const float* cb1 = (const float*)d_in[10];
    const float* cW2 = (const float*)d_in[11];
    const float* iW1 = (const float*)d_in[12];
    const float* ib1 = (const float*)d_in[13];
    const float* iW2 = (const float*)d_in[14];
    const float* ib2 = (const float*)d_in[15];
    const float* nW1 = (const float*)d_in[16];
    const float* nb1 = (const float*)d_in[17];
    const float* nW2 = (const float*)d_in[18];
    const float* nb2 = (const float*)d_in[19];
    const float* vW1 = (const float*)d_in[20];
    const float* vb1 = (const float*)d_in[21];
    const float* vW2 = (const float*)d_in[22];
    int N = in_sizes[0] / 128;
    int E = in_sizes[2];
    float* out   = (float*)d_out;
    float* out_h = out;
    float* out_x = out + (size_t)N * 128;
    float* out_v = out_x + (size_t)N * 3;

    cudaFuncSetAttribute(egnn_edge_mma, cudaFuncAttributeMaxDynamicSharedMemorySize, E_SMEM);
    cudaFuncSetAttribute(egnn_node_kernel, cudaFuncAttributeMaxDynamicSharedMemorySize, ND_SMEM);

    prep_weights<<<288, 256>>>(eW1, eW2, cW1, iW1);
    egnn_zero_kernel<<<512, 256>>>(N);
    egnn_edge_mma<<<(E + 127) / 128, 256, E_SMEM>>>(
        h, x, eattr, ei, E, eW1, eb1, eb2, cb1, cW2, ib1, iW2, ib2);
    egnn_node_kernel<<<(N + TEN - 1) / TEN, 256, ND_SMEM>>>(
        h, x, vinit, N, nW1, nb1, nW2, nb2, vW1, vb1, vW2, out_h, out_x, out_v);
}

// round 7
// speedup vs baseline: 4.8679x; 1.9011x over previous
#include <cuda_runtime.h>
#include <cuda_fp16.h>
#include <cstdint>

// ===========================================================================
// EGNN layer. Edge MLPs on mma.sync fp16 (2-pass hi/lo split on A; B fp16).
// Error ~1e-4 (threshold 1e-3). Node MLPs scalar fp32.
// Output: concat(h_out[N,128], x_out[N,3], v_out[N,3]).
// ===========================================================================

#define MAXN 50016
__device__ float  g_mi[(size_t)MAXN * 128];
__device__ float4 g_agg[MAXN];
// weight images: W^T [N][K] row-major fp16, row stride 136 elems (272B).
// e1a@0, e1b@34816, e2@69632, c1@104448 (each 34816), i1@139264 (17408).
__device__ __align__(16) unsigned char g_wimg[156672];

#define IMG_E1A 0
#define IMG_E1B 34816
#define IMG_E2  69632
#define IMG_C1  104448
#define IMG_I1  139264
#define BROW    272

// ---- smem layout (bytes), total 113280 -> 2 CTAs/SM ----
#define SA_HI   0
#define SA_LO   34816
#define SB      69632
#define SCST    104448       // 928 floats
#define SXDA    108160       // 128*8 floats
#define SRIDX   112256
#define SCIDX   112768
#define E_SMEM  113280

__device__ __forceinline__ uint32_t smem_u32(const void* p) {
    uint32_t a;
    asm("{ .reg .u64 t; cvta.to.shared.u64 t, %1; cvt.u32.u64 %0, t; }" : "=r"(a) : "l"(p));
    return a;
}
__device__ __forceinline__ void ldm4(uint32_t r[4], uint32_t addr) {
    asm volatile("ldmatrix.sync.aligned.m8n8.x4.shared.b16 {%0,%1,%2,%3}, [%4];"
        : "=r"(r[0]), "=r"(r[1]), "=r"(r[2]), "=r"(r[3]) : "r"(addr));
}
__device__ __forceinline__ void mma16816(float4& d, const uint32_t a[4], uint32_t b0, uint32_t b1) {
    asm volatile("mma.sync.aligned.m16n8k16.row.col.f32.f16.f16.f32 "
        "{%0,%1,%2,%3}, {%4,%5,%6,%7}, {%8,%9}, {%0,%1,%2,%3};"
        : "+f"(d.x), "+f"(d.y), "+f"(d.z), "+f"(d.w)
        : "r"(a[0]), "r"(a[1]), "r"(a[2]), "r"(a[3]), "r"(b0), "r"(b1));
}
#define CP16(dst, src) \
    asm volatile("cp.async.cg.shared.global [%0], [%1], 16;" :: "r"(dst), "l"(src))
#define CP_COMMIT() asm volatile("cp.async.commit_group;" ::: "memory")
#define CP_WAIT(n)  asm volatile("cp.async.wait_group %0;" :: "n"(n) : "memory")

// ---- MUFU-free silu ----
__device__ __forceinline__ float fexp_neg(float v) {
    float t = fminf(fmaxf(v, -30.f), 30.f) * -1.44269504f;
    float r = t + 12582912.f;
    int   k = __float_as_int(r) - 0x4B400000;
    float f = t - (r - 12582912.f);
    float g = f * 0.69314718f;
    float p = 1.f + g * (1.f + g * (0.5f + g * (0.16666667f + g * (0.041666667f
            + g * (8.3333333e-3f + g * 1.3888889e-3f)))));
    return p * __int_as_float((k + 127) << 23);
}
__device__ __forceinline__ float frcp(float d) {
    float y = __int_as_float(0x7EF311C3 - __float_as_int(d));
    y = y * (2.f - d * y); y = y * (2.f - d * y); y = y * (2.f - d * y);
    return y;
}
__device__ __forceinline__ float fsig(float v)  { return frcp(1.f + fexp_neg(v)); }
__device__ __forceinline__ float siluf(float v) { return v * fsig(v); }

// ---- weight prep: W[K,N] -> W^T[N,K] fp16 padded images ----
__global__ void prep_weights(const float* __restrict__ eW1, const float* __restrict__ eW2,
                             const float* __restrict__ cW1, const float* __restrict__ iW1) {
    int i = blockIdx.x * blockDim.x + threadIdx.x;
    int base, n, k; float w;
    if (i < 16384) {
        k = i >> 7; n = i & 127; base = IMG_E1A; w = eW1[k * 128 + n];
    } else if (i < 32768) {
        int j = i - 16384; k = j >> 7; n = j & 127; base = IMG_E1B; w = eW1[(128 + k) * 128 + n];
    } else if (i < 49152) {
        int j = i - 32768; k = j >> 7; n = j & 127; base = IMG_E2; w = eW2[k * 128 + n];
    } else if (i < 65536) {
        int j = i - 49152; k = j >> 7; n = j & 127; base = IMG_C1; w = cW1[k * 128 + n];
    } else if (i < 73728) {
        int j = i - 65536; k = j >> 6; n = j & 63; base = IMG_I1; w = iW1[k * 64 + n];
    } else return;
    *(__half*)(g_wimg + base + n * BROW + k * 2) = __float2half(w);
}

__global__ void egnn_zero_kernel(int N) {
    int total = N * 32;
    for (int i = blockIdx.x * blockDim.x + threadIdx.x; i < total + N; i += gridDim.x * blockDim.x) {
        if (i < total) ((float4*)g_mi)[i] = make_float4(0.f, 0.f, 0.f, 0.f);
        else           g_agg[i - total]   = make_float4(0.f, 0.f, 0.f, 0.f);
    }
}

// ---- 2-pass split GEMM: acc[NT] += (Ahi+Alo)[16,128] @ B[128, NT*8] ----
template <int NT>
__device__ __forceinline__ void gemm2p(float4* acc, uint32_t aHi, uint32_t aLo,
                                       uint32_t bHi, int lane) {
    const uint32_t aoff = ((lane & 7) + ((lane >> 3) & 1) * 8) * BROW + ((lane >> 4) & 1) * 16;
    const uint32_t boff = ((lane & 7) + ((lane >> 4) & 1) * 8) * BROW + ((lane >> 3) & 1) * 16;
#pragma unroll
    for (int ks = 0; ks < 8; ++ks) {
        uint32_t ah[4], al[4];
        ldm4(ah, aHi + aoff + ks * 32);
        ldm4(al, aLo + aoff + ks * 32);
#pragma unroll
        for (int p = 0; p < NT / 2; ++p) {
            uint32_t bh[4];
            ldm4(bh, bHi + p * 16 * BROW + boff + ks * 32);
            mma16816(acc[2 * p],     ah, bh[0], bh[1]);
            mma16816(acc[2 * p + 1], ah, bh[2], bh[3]);
            mma16816(acc[2 * p],     al, bh[0], bh[1]);
            mma16816(acc[2 * p + 1], al, bh[2], bh[3]);
        }
    }
}

// split fp32 -> fp16 hi/lo pair, store 4B each to A buffers
__device__ __forceinline__ void splitst(char* smc, int row, int col, float v0, float v1) {
    __half h0 = __float2half(v0), h1 = __float2half(v1);
    __half2 hp; hp.x = h0; hp.y = h1;
    __half2 lp;
    lp.x = __float2half(v0 - __half2float(h0));
    lp.y = __float2half(v1 - __half2float(h1));
    int off = row * BROW + col * 2;
    *(__half2*)(smc + SA_HI + off) = hp;
    *(__half2*)(smc + SA_LO + off) = lp;
}

__device__ __forceinline__ void gatherA(char* smc, const float* __restrict__ h,
                                        const int* idx, int wid, int lane) {
    int row = wid * 16 + (lane >> 1);
    int c0 = (lane & 1) * 64;
    const float4* src = (const float4*)(h + (size_t)idx[row] * 128 + c0);
#pragma unroll
    for (int q = 0; q < 16; ++q) {
        float4 f = __ldg(src + q);
        splitst(smc, row, c0 + q * 4, f.x, f.y);
        splitst(smc, row, c0 + q * 4 + 2, f.z, f.w);
    }
}
__device__ __forceinline__ void cpyB(uint32_t dst, const unsigned char* src, int bytes, int tid) {
    for (int i = tid * 16; i < bytes; i += 256 * 16) CP16(dst + i, src + i);
    CP_COMMIT();
}

__global__ void __launch_bounds__(256, 2)
egnn_edge_mma(const float* __restrict__ h, const float* __restrict__ x,
              const float* __restrict__ eattr, const int* __restrict__ ei, int E,
              const float* __restrict__ eW1, const float* __restrict__ eb1,
              const float* __restrict__ eb2,
              const float* __restrict__ cb1, const float* __restrict__ cW2,
              const float* __restrict__ ib1, const float* __restrict__ iW2,
              const float* __restrict__ ib2) {
    extern __shared__ __align__(16) char smc[];
    uint32_t sb = smem_u32(smc);
    const int tid = threadIdx.x, wid = tid >> 5, lane = tid & 31;
    float* cst = (float*)(smc + SCST);
    float* xda = (float*)(smc + SXDA);
    int* ridx = (int*)(smc + SRIDX);
    int* cidx = (int*)(smc + SCIDX);
    const int e0 = blockIdx.x * 128;

    cpyB(sb + SB, g_wimg + IMG_E1A, 34816, tid);

    if (tid < 128) {
        cst[tid]       = __ldg(eb1 + tid);
        cst[128 + tid] = __ldg(eb2 + tid);
        cst[256 + tid] = __ldg(cb1 + tid);
        cst[384 + tid] = __ldg(cW2 + tid);
        cst[512 + tid] = __ldg(eW1 + 256 * 128 + tid);
        cst[640 + tid] = __ldg(eW1 + 257 * 128 + tid);
        if (tid < 64) { cst[768 + tid] = __ldg(ib1 + tid); cst[832 + tid] = __ldg(iW2 + tid); }
        if (tid == 0) cst[896] = __ldg(ib2);
        int e = e0 + tid, r = 0, c = 0;
        float at = 0.f, valid = 0.f;
        if (e < E) { r = __ldg(ei + e); c = __ldg(ei + E + e); at = __ldg(eattr + e); valid = 1.f; }
        float dx = x[r * 3 + 0] - x[c * 3 + 0];
        float dy = x[r * 3 + 1] - x[c * 3 + 1];
        float dz = x[r * 3 + 2] - x[c * 3 + 2];
        xda[tid * 8 + 0] = dx; xda[tid * 8 + 1] = dy; xda[tid * 8 + 2] = dz;
        xda[tid * 8 + 3] = dx * dx + dy * dy + dz * dz;
        xda[tid * 8 + 4] = at; xda[tid * 8 + 7] = valid;
        ridx[tid] = r; cidx[tid] = c;
    }
    __syncthreads();                       // ridx/cidx visible
    gatherA(smc, h, ridx, wid, lane);      // A = h[row] (warp-private rows)
    CP_WAIT(0); __syncthreads();           // B = eW1a ready

    const uint32_t aHi = sb + SA_HI + wid * 16 * BROW;
    const uint32_t aLo = sb + SA_LO + wid * 16 * BROW;
    float4 acc[16];
#pragma unroll
    for (int t = 0; t < 16; ++t) acc[t] = make_float4(0.f, 0.f, 0.f, 0.f);

    // stage 1a: h[row] @ eW1[k 0..127]
    gemm2p<16>(acc, aHi, aLo, sb + SB, lane);
    __syncthreads();                       // B consumed
    cpyB(sb + SB, g_wimg + IMG_E1B, 34816, tid);
    gatherA(smc, h, cidx, wid, lane);      // A = h[col] (overlaps cp.async)
    CP_WAIT(0); __syncthreads();

    // stage 1b: + h[col] @ eW1[k 128..255]; tail + bias + silu -> m1 -> A
    gemm2p<16>(acc, aHi, aLo, sb + SB, lane);
    __syncthreads();
    cpyB(sb + SB, g_wimg + IMG_E2, 34816, tid);
    {
        int r0 = wid * 16 + lane / 4, r1 = r0 + 8;
        float d0 = xda[r0 * 8 + 3], a0 = xda[r0 * 8 + 4];
        float d1 = xda[r1 * 8 + 3], a1 = xda[r1 * 8 + 4];
#pragma unroll
        for (int t = 0; t < 16; ++t) {
            int c = t * 8 + (lane & 3) * 2;
            float b0 = cst[c], b1 = cst[c + 1];
            float wA0 = cst[512 + c], wA1 = cst[512 + c + 1];
            float wB0 = cst[640 + c], wB1 = cst[640 + c + 1];
            splitst(smc, r0, c, siluf(acc[t].x + b0 + d0 * wA0 + a0 * wB0),
                                siluf(acc[t].y + b1 + d0 * wA1 + a0 * wB1));
            splitst(smc, r1, c, siluf(acc[t].z + b0 + d1 * wA0 + a1 * wB0),
                                siluf(acc[t].w + b1 + d1 * wA1 + a1 * wB1));
            acc[t] = make_float4(0.f, 0.f, 0.f, 0.f);
        }
    }
    CP_WAIT(0); __syncthreads();           // B = eW2

    // stage 2: m_ij = silu(m1 @ eW2 + b2) -> A
    gemm2p<16>(acc, aHi, aLo, sb + SB, lane);
    __syncthreads();
    cpyB(sb + SB, g_wimg + IMG_C1, 34816, tid);
    {
        int r0 = wid * 16 + lane / 4, r1 = r0 + 8;
#pragma unroll
        for (int t = 0; t < 16; ++t) {
            int c = t * 8 + (lane & 3) * 2;
            float b0 = cst[128 + c], b1 = cst[128 + c + 1];
            splitst(smc, r0, c, siluf(acc[t].x + b0), siluf(acc[t].y + b1));
            splitst(smc, r1, c, siluf(acc[t].z + b0), siluf(acc[t].w + b1));
            acc[t] = make_float4(0.f, 0.f, 0.f, 0.f);
        }
    }
    CP_WAIT(0); __syncthreads();           // B = cW1; m_ij CTA-visible

    // stage 3: c1 = silu(m_ij @ cW1 + cb1); phi = c1 . cW2
    gemm2p<16>(acc, aHi, aLo, sb + SB, lane);
    __syncthreads();
    cpyB(sb + SB, g_wimg + IMG_I1, 17408, tid);
    {
        int r0 = wid * 16 + lane / 4, r1 = r0 + 8;
        float p0 = 0.f, p1 = 0.f;
#pragma unroll
        for (int t = 0; t < 16; ++t) {
            int c = t * 8 + (lane & 3) * 2;
            float b0 = cst[256 + c], b1 = cst[256 + c + 1];
            float w0 = cst[384 + c], w1 = cst[384 + c + 1];
            p0 += siluf(acc[t].x + b0) * w0 + siluf(acc[t].y + b1) * w1;
            p1 += siluf(acc[t].z + b0) * w0 + siluf(acc[t].w + b1) * w1;
            acc[t] = make_float4(0.f, 0.f, 0.f, 0.f);
        }
        p0 += __shfl_xor_sync(0xFFFFFFFF, p0, 1); p1 += __shfl_xor_sync(0xFFFFFFFF, p1, 1);
        p0 += __shfl_xor_sync(0xFFFFFFFF, p0, 2); p1 += __shfl_xor_sync(0xFFFFFFFF, p1, 2);
        if ((lane & 3) == 0) { xda[r0 * 8 + 6] = p0; xda[r1 * 8 + 6] = p1; }
    }
    CP_WAIT(0); __syncthreads();           // B = iW1; phi visible

    // stage 4: s1 = silu(m_ij @ iW1 + ib1); e = sigmoid(s1 . iW2 + ib2)
    gemm2p<8>(acc, aHi, aLo, sb + SB, lane);
    {
        int r0 = wid * 16 + lane / 4, r1 = r0 + 8;
        float s0 = 0.f, s1 = 0.f;
#pragma unroll
        for (int t = 0; t < 8; ++t) {
            int c = t * 8 + (lane & 3) * 2;
            float b0 = cst[768 + c], b1 = cst[768 + c + 1];
            float w0 = cst[832 + c], w1 = cst[832 + c + 1];
            s0 += siluf(acc[t].x + b0) * w0 + siluf(acc[t].y + b1) * w1;
            s1 += siluf(acc[t].z + b0) * w0 + siluf(acc[t].w + b1) * w1;
        }
        s0 += __shfl_xor_sync(0xFFFFFFFF, s0, 1); s1 += __shfl_xor_sync(0xFFFFFFFF, s1, 1);
        s0 += __shfl_xor_sync(0xFFFFFFFF, s0, 2); s1 += __shfl_xor_sync(0xFFFFFFFF, s1, 2);
        float bi = cst[896];
        if ((lane & 3) == 0) { xda[r0 * 8 + 5] = fsig(s0 + bi); xda[r1 * 8 + 5] = fsig(s1 + bi); }
    }
    __syncthreads();                       // e visible

    // ---- scatter ----
    if (tid < 128 && xda[tid * 8 + 7] != 0.f) {
        float s = xda[tid * 8 + 5] * xda[tid * 8 + 6];
        atomicAdd(&g_agg[ridx[tid]],
                  make_float4(s * xda[tid * 8 + 0], s * xda[tid * 8 + 1],
                              s * xda[tid * 8 + 2], 1.0f));
    }
    for (int q = tid; q < 128 * 32; q += 256) {
        int t = q >> 5, k4 = q & 31;
        if (xda[t * 8 + 7] == 0.f) continue;
        float e = xda[t * 8 + 5];
        int off = t * BROW + k4 * 8;
        __half2 h0 = *(__half2*)(smc + SA_HI + off);
        __half2 h1 = *(__half2*)(smc + SA_HI + off + 4);
        __half2 l0 = *(__half2*)(smc + SA_LO + off);
        __half2 l1 = *(__half2*)(smc + SA_LO + off + 4);
        float4 m;
        m.x = (__half2float(h0.x) + __half2float(l0.x)) * e;
        m.y = (__half2float(h0.y) + __half2float(l0.y)) * e;
        m.z = (__half2float(h1.x) + __half2float(l1.x)) * e;
        m.w = (__half2float(h1.y) + __half2float(l1.y)) * e;
        atomicAdd(((float4*)g_mi) + (size_t)ridx[t] * 32 + k4, m);
    }
}

// ---------------- node kernel (validated scalar fp32) ----------------
#define TEN 64
#define LDN 132
#define NO_A 0
#define NO_B (TEN * LDN)
#define NO_C (2 * TEN * LDN)
#define NO_W (3 * TEN * LDN)
#define ND_SMEM ((NO_W + 1024 + 64) * 4)

__device__ __forceinline__ void nd_init(float acc[4][8], const float* __restrict__ bias, int tx) {
    float4 b0 = __ldg((const float4*)bias + tx * 2);
    float4 b1 = __ldg((const float4*)bias + tx * 2 + 1);
#pragma unroll
    for (int i = 0; i < 4; ++i) {
        acc[i][0] = b0.x; acc[i][1] = b0.y; acc[i][2] = b0.z; acc[i][3] = b0.w;
        acc[i][4] = b1.x; acc[i][5] = b1.y; acc[i][6] = b1.z; acc[i][7] = b1.w;
    }
}
__device__ __forceinline__ void nd_gemm(float acc[4][8], const float* __restrict__ As,
                                        const float* __restrict__ Wg, int K,
                                        float* wt, int tid, int ty, int tx) {
    for (int k0 = 0; k0 < K; k0 += 8) {
        __syncthreads();
        ((float4*)wt)[tid] = __ldg((const float4*)(Wg + k0 * 128) + tid);
        __syncthreads();
        const float* ap = As + (ty * 4) * LDN + k0;
#pragma unroll
        for (int k = 0; k < 8; ++k) {
            float a[4] = {ap[k], ap[LDN + k], ap[2 * LDN + k], ap[3 * LDN + k]};
            float4 b0 = *(const float4*)(wt + k * 128 + tx * 8);
            float4 b1 = *(const float4*)(wt + k * 128 + tx * 8 + 4);
            float b[8] = {b0.x, b0.y, b0.z, b0.w, b1.x, b1.y, b1.z, b1.w};
#pragma unroll
            for (int i = 0; i < 4; ++i)
#pragma unroll
                for (int j = 0; j < 8; ++j) acc[i][j] += a[i] * b[j];
        }
    }
}
template <bool ACT>
__device__ __forceinline__ void nd_store(const float acc[4][8], float* C, int ty, int tx) {
#pragma unroll
    for (int i = 0; i < 4; ++i) {
        float4 v0, v1;
        v0.x = ACT ? siluf(acc[i][0]) : acc[i][0]; v0.y = ACT ? siluf(acc[i][1]) : acc[i][1];
        v0.z = ACT ? siluf(acc[i][2]) : acc[i][2]; v0.w = ACT ? siluf(acc[i][3]) : acc[i][3];
        v1.x = ACT ? siluf(acc[i][4]) : acc[i][4]; v1.y = ACT ? siluf(acc[i][5]) : acc[i][5];
        v1.z = ACT ? siluf(acc[i][6]) : acc[i][6]; v1.w = ACT ? siluf(acc[i][7]) : acc[i][7];
        float* p = C + (ty * 4 + i) * LDN + tx * 8;
        *(float4*)p = v0; *(float4*)(p + 4) = v1;
    }
}
__global__ void __launch_bounds__(256, 2)
egnn_node_kernel(const float* __restrict__ h, const float* __restrict__ x,
                 const float* __restrict__ vinit, int N,
                 const float* __restrict__ nW1, const float* __restrict__ nb1,
                 const float* __restrict__ nW2, const float* __restrict__ nb2,
                 const float* __restrict__ vW1, const float* __restrict__ vb1,
                 const float* __restrict__ vW2,
                 float* __restrict__ out_h, float* __restrict__ out_x, float* __restrict__ out_v) {
    extern __shared__ float smf[];
    float* bufA = smf + NO_A; float* bufB = smf + NO_B;
    float* bufC = smf + NO_C; float* wt = smf + NO_W;
    const int tid = threadIdx.x, tx = tid & 15, ty = tid >> 4;
    const int n0 = blockIdx.x * TEN;
    for (int q = tid; q < TEN * 32; q += 256) {
        int t = q >> 5, k4 = q & 31, n = n0 + t;
        if (n >= N) n = N - 1;
        ((float4*)(bufA + t * LDN))[k4] = __ldg((const float4*)h + n * 32 + k4);
        ((float4*)(bufB + t * LDN))[k4] = ((const float4*)g_mi)[n * 32 + k4];
    }
    float acc[4][8];
    nd_init(acc, vb1, tx);
    nd_gemm(acc, bufA, vW1, 128, wt, tid, ty, tx);
    nd_store<true>(acc, bufC, ty, tx);
    __syncthreads();
    if (tid < 128) wt[tid] = __ldg(vW2 + tid);
    __syncthreads();
    if (tid < TEN) {
        int n = n0 + tid;
        if (n < N) {
            const float* trow = bufC + tid * LDN;
            float s = 0.f;
#pragma unroll 8
            for (int k = 0; k < 128; ++k) s += trow[k] * wt[k];
            float vx = vinit[n * 3 + 0] * s, vy = vinit[n * 3 + 1] * s, vz = vinit[n * 3 + 2] * s;
            out_v[n * 3 + 0] = vx; out_v[n * 3 + 1] = vy; out_v[n * 3 + 2] = vz;
            float4 ag = g_agg[n];
            float inv = 1.0f / (float)(N - 1);
            float x0 = x[n * 3 + 0], x1 = x[n * 3 + 1], x2 = x[n * 3 + 2];
            if (ag.w > 0.f) {
                out_x[n * 3 + 0] = x0 + vx + ag.x * inv;
                out_x[n * 3 + 1] = x1 + vy + ag.y * inv;
                out_x[n * 3 + 2] = x2 + vz + ag.z * inv;
            } else {
                out_x[n * 3 + 0] = x0; out_x[n * 3 + 1] = x1; out_x[n * 3 + 2] = x2;
            }
        }
    }
    __syncthreads();
    nd_init(acc, nb1, tx);
    nd_gemm(acc, bufA, nW1, 128, wt, tid, ty, tx);
    nd_gemm(acc, bufB, nW1 + 128 * 128, 128, wt, tid, ty, tx);
    nd_store<true>(acc, bufC, ty, tx);
    nd_init(acc, nb2, tx);
    nd_gemm(acc, bufC, nW2, 128, wt, tid, ty, tx);
#pragma unroll
    for (int i = 0; i < 4; ++i) {
        int n = n0 + ty * 4 + i;
        if (n < N) {
            float4* p = (float4*)(out_h + (size_t)n * 128);
            p[tx * 2]     = make_float4(acc[i][0], acc[i][1], acc[i][2], acc[i][3]);
            p[tx * 2 + 1] = make_float4(acc[i][4], acc[i][5], acc[i][6], acc[i][7]);
        }
    }
}

extern "C" void kernel_launch(void* const* d_in, const int* in_sizes, int n_in,
                              void* d_out, int out_size) {
    const float* h     = (const float*)d_in[0];
    const float* x     = (const float*)d_in[1];
    const float* eattr = (const float*)d_in[2];
    const float* vinit = (const float*)d_in[3];
    const int*   ei    = (const int*)d_in[4];
    const float* eW1 = (const float*)d_in[5];
    const float* eb1 = (const float*)d_in[6];
    const float* eW2 = (const float*)d_in[7];
    const float* eb2 = (const float*)d_in[8];
    const float* cW1 = (const float*)d_in[9];
    const float* cb1 = (const float*)d_in[10];
    const float* cW2 = (const float*)d_in[11];
    const float* iW1 = (const float*)d_in[12];
    const float* ib1 = (const float*)d_in[13];
    const float* iW2 = (const float*)d_in[14];
    const float* ib2 = (const float*)d_in[15];
    const float* nW1 = (const float*)d_in[16];
    const float* nb1 = (const float*)d_in[17];
    const float* nW2 = (const float*)d_in[18];
    const float* nb2 = (const float*)d_in[19];
    const float* vW1 = (const float*)d_in[20];
    const float* vb1 = (const float*)d_in[21];
    const float* vW2 = (const float*)d_in[22];
    int N = in_sizes[0] / 128;
    int E = in_sizes[2];
    float* out   = (float*)d_out;
    float* out_h = out;
    float* out_x = out + (size_t)N * 128;
    float* out_v = out_x + (size_t)N * 3;

    cudaFuncSetAttribute(egnn_edge_mma, cudaFuncAttributeMaxDynamicSharedMemorySize, E_SMEM);
    cudaFuncSetAttribute(egnn_node_kernel, cudaFuncAttributeMaxDynamicSharedMemorySize, ND_SMEM);

    prep_weights<<<288, 256>>>(eW1, eW2, cW1, iW1);
    egnn_zero_kernel<<<512, 256>>>(N);
    egnn_edge_mma<<<(E + 127) / 128, 256, E_SMEM>>>(
        h, x, eattr, ei, E, eW1, eb1, eb2, cb1, cW2, ib1, iW2, ib2);
    egnn_node_kernel<<<(N + TEN - 1) / TEN, 256, ND_SMEM>>>(
        h, x, vinit, N, nW1, nb1, nW2, nb2, vW1, vb1, vW2, out_h, out_x, out_v);
}